// round 10
// baseline (speedup 1.0000x reference)
#include <cuda_runtime.h>
#include <cuda_bf16.h>
#include <cstdint>

#define BATCH 8
#define SEQ   2048
#define DIM   512
#define NQKV  1536   // 3*DIM

// ---------------------------------------------------------------------------
// Scratch (device globals)
// ---------------------------------------------------------------------------
__device__ __align__(16) float g_QKV[(long)BATCH * SEQ * NQKV];  // 96 MB
__device__ __align__(16) float g_Vt [(long)BATCH * DIM * SEQ];   // 32 MB
__device__ __align__(16) float g_S  [(long)BATCH * SEQ * SEQ];   // 128 MB
__device__ __align__(16) float g_WT [(long)NQKV * DIM];          // 3 MB

// ---------------------------------------------------------------------------
// PTX helpers (baseline ISA: ldmatrix + mma.sync, sm_80+)
// ---------------------------------------------------------------------------
__device__ __forceinline__ uint32_t smem_u32(const void* p) {
    uint32_t a;
    asm("{ .reg .u64 t; cvta.to.shared.u64 t, %1; cvt.u32.u64 %0, t; }"
        : "=r"(a) : "l"(p));
    return a;
}
__device__ __forceinline__ void ldsm_x4(uint32_t addr, uint32_t* r) {
    asm volatile("ldmatrix.sync.aligned.m8n8.x4.shared.b16 {%0,%1,%2,%3}, [%4];"
                 : "=r"(r[0]), "=r"(r[1]), "=r"(r[2]), "=r"(r[3]) : "r"(addr));
}
__device__ __forceinline__ void mma_bf16(float* c, const uint32_t* a, const uint32_t* b) {
    asm volatile(
        "mma.sync.aligned.m16n8k16.row.col.f32.bf16.bf16.f32 "
        "{%0,%1,%2,%3}, {%4,%5,%6,%7}, {%8,%9}, {%0,%1,%2,%3};"
        : "+f"(c[0]), "+f"(c[1]), "+f"(c[2]), "+f"(c[3])
        : "r"(a[0]), "r"(a[1]), "r"(a[2]), "r"(a[3]), "r"(b[0]), "r"(b[1]));
}

// Convert float4 -> hi/lo bf16 pairs and store 8B each to smem
__device__ __forceinline__ void cvt_store(char* hi, char* lo, uint32_t off, float4 v) {
    __nv_bfloat162 h01 = __floats2bfloat162_rn(v.x, v.y);
    __nv_bfloat162 h23 = __floats2bfloat162_rn(v.z, v.w);
    __nv_bfloat162 l01 = __floats2bfloat162_rn(v.x - __bfloat162float(h01.x),
                                               v.y - __bfloat162float(h01.y));
    __nv_bfloat162 l23 = __floats2bfloat162_rn(v.z - __bfloat162float(h23.x),
                                               v.w - __bfloat162float(h23.y));
    *reinterpret_cast<uint2*>(hi + off) =
        make_uint2(*reinterpret_cast<uint32_t*>(&h01), *reinterpret_cast<uint32_t*>(&h23));
    *reinterpret_cast<uint2*>(lo + off) =
        make_uint2(*reinterpret_cast<uint32_t*>(&l01), *reinterpret_cast<uint32_t*>(&l23));
}

// ---------------------------------------------------------------------------
// Tensor-core GEMM: C[M,N] = alpha * A[M,K] @ B[N,K]^T  (fp32 in/out)
// In-kernel split precision (hi+lo bf16, 3 MMA terms), CTA tile 128x128,
// k-chunk 32, double-buffered smem, 1 sync per chunk.
// 256 threads / 8 warps (2M x 4N grid of 64x32 warp tiles -> low ldsm
// redundancy), TWO CTAs co-resident per SM (launch_bounds(256,2), 80KB smem
// each) so 4 warps/SMSP hide MMA/ldsm/barrier latency across CTAs.
// ---------------------------------------------------------------------------
#define ROWB   80                  // padded smem row bytes (40 bf16): conflict-free ldsm
#define TILEB  (128 * ROWB)        // 10240
#define STAGEB (4 * TILEB)         // Ahi, Alo, Bhi, Blo
#define SMEMB  (2 * STAGEB)        // 81920

__global__ __launch_bounds__(256, 2)
void tc_gemm7(const float* __restrict__ A, const float* __restrict__ B,
              float* __restrict__ C, int M, int N, int K,
              int ldA, int ldB, int ldC, long sA, long sB, long sC, float alpha)
{
    extern __shared__ __align__(16) char smem[];

    const long zb = blockIdx.z;
    A += zb * sA;
    B += zb * sB;
    C += zb * sC;

    const int tid  = threadIdx.x;
    const int wid  = tid >> 5;
    const int lane = tid & 31;
    const int wm   = wid & 1;   // 2 warps along M (64 rows each)
    const int wn   = wid >> 1;  // 4 warps along N (32 cols each)

    const int rowA = blockIdx.y * 128;
    const int rowB = blockIdx.x * 128;

    // Loader mapping: 32-float rows; 8 threads per row; 4 row-iterations
    const int lrow = tid >> 3;        // 0..31, advance by 32 per i
    const int lc4  = tid & 7;         // float4 index within 32-float row

    // ldmatrix lane selectors
    const int aRow = lane & 15;
    const int aK   = (lane >> 4) * 8;
    const int bRow = (lane & 7) + ((lane >> 4) & 1) * 8;
    const int bK   = ((lane >> 3) & 1) * 8;

    float acc[4][4][4];
#pragma unroll
    for (int i = 0; i < 4; i++)
#pragma unroll
        for (int j = 0; j < 4; j++)
#pragma unroll
            for (int k = 0; k < 4; k++) acc[i][j][k] = 0.0f;

    const int nchunk = K / 32;
    float4 sa[4], sb[4];

    auto prefetch = [&](int c) {
        const int kb = c * 32;
#pragma unroll
        for (int i = 0; i < 4; i++) {
            const int r = lrow + i * 32;
            sa[i] = *reinterpret_cast<const float4*>(&A[(long)(rowA + r) * ldA + kb + lc4 * 4]);
            sb[i] = *reinterpret_cast<const float4*>(&B[(long)(rowB + r) * ldB + kb + lc4 * 4]);
        }
    };

    auto cvtstore = [&](int st) {
        char* base = smem + st * STAGEB;
#pragma unroll
        for (int i = 0; i < 4; i++) {
            const int r = lrow + i * 32;
            const uint32_t off = (uint32_t)(r * ROWB + lc4 * 8);
            cvt_store(base + 0 * TILEB, base + 1 * TILEB, off, sa[i]);
            cvt_store(base + 2 * TILEB, base + 3 * TILEB, off, sb[i]);
        }
    };

    prefetch(0);
    cvtstore(0);
    __syncthreads();

    const uint32_t sbase = smem_u32(smem);

    for (int c = 0; c < nchunk; c++) {
        const int st = c & 1;

        if (c + 1 < nchunk) prefetch(c + 1);   // LDG latency hides under MMA

        const uint32_t uA  = sbase + st * STAGEB;
        const uint32_t uAl = uA + TILEB;
        const uint32_t uB  = uA + 2 * TILEB;
        const uint32_t uBl = uA + 3 * TILEB;

#pragma unroll
        for (int ks = 0; ks < 2; ks++) {
            // B fragments first (16 regs live), then stream A per mi (8 regs)
            uint32_t bh[4][2], bl[4][2];
#pragma unroll
            for (int nj = 0; nj < 2; nj++) {
                const uint32_t off = (uint32_t)((wn * 32 + nj * 16 + bRow) * ROWB
                                                + (ks * 16 + bK) * 2);
                uint32_t rh[4], rl[4];
                ldsm_x4(uB + off, rh);
                ldsm_x4(uBl + off, rl);
                bh[nj * 2][0] = rh[0]; bh[nj * 2][1] = rh[1];
                bh[nj * 2 + 1][0] = rh[2]; bh[nj * 2 + 1][1] = rh[3];
                bl[nj * 2][0] = rl[0]; bl[nj * 2][1] = rl[1];
                bl[nj * 2 + 1][0] = rl[2]; bl[nj * 2 + 1][1] = rl[3];
            }
#pragma unroll
            for (int mi = 0; mi < 4; mi++) {
                uint32_t ah[4], al[4];
                const uint32_t off = (uint32_t)((wm * 64 + mi * 16 + aRow) * ROWB
                                                + (ks * 16 + aK) * 2);
                ldsm_x4(uA + off, ah);
                ldsm_x4(uAl + off, al);
#pragma unroll
                for (int ni = 0; ni < 4; ni++) {
                    mma_bf16(acc[mi][ni], ah, bh[ni]);
                    mma_bf16(acc[mi][ni], ah, bl[ni]);
                    mma_bf16(acc[mi][ni], al, bh[ni]);
                }
            }
        }

        if (c + 1 < nchunk) cvtstore(st ^ 1);  // overlaps with tail of MMA stream
        __syncthreads();
    }

    // Epilogue (fp32)
    const int g = lane >> 2, t = lane & 3;
#pragma unroll
    for (int mi = 0; mi < 4; mi++) {
#pragma unroll
        for (int half = 0; half < 2; half++) {
            const long r = (long)(rowA + wm * 64 + mi * 16 + g + half * 8);
#pragma unroll
            for (int ni = 0; ni < 4; ni++) {
                const int col = rowB + wn * 32 + ni * 8 + t * 2;
                *reinterpret_cast<float2*>(&C[r * ldC + col]) =
                    make_float2(acc[mi][ni][half * 2 + 0] * alpha,
                                acc[mi][ni][half * 2 + 1] * alpha);
            }
        }
    }
}

// ---------------------------------------------------------------------------
// Transpose: out[c,r] = in[r,c]; input ld = ldIn, output ld = R; batched via z
// ---------------------------------------------------------------------------
__global__ __launch_bounds__(256)
void transpose_kernel(const float* __restrict__ in, float* __restrict__ out,
                      int R, int ldIn, long sIn, long sOut)
{
    __shared__ float t[32][33];
    in  += (long)blockIdx.z * sIn;
    out += (long)blockIdx.z * sOut;
    const int rb = blockIdx.y * 32, cb = blockIdx.x * 32;
    const int x = threadIdx.x, y = threadIdx.y;  // 32 x 8
#pragma unroll
    for (int j = 0; j < 32; j += 8)
        t[y + j][x] = in[(long)(rb + y + j) * ldIn + cb + x];
    __syncthreads();
#pragma unroll
    for (int j = 0; j < 32; j += 8)
        out[(long)(cb + y + j) * R + rb + x] = t[x][y + j];
}

// ---------------------------------------------------------------------------
// Row softmax over SEQ=2048 columns, in-place fp32. One 256-thread CTA/row.
// ---------------------------------------------------------------------------
__global__ __launch_bounds__(256)
void softmax_kernel(float* __restrict__ S)
{
    float* p = S + (long)blockIdx.x * SEQ;
    const int tid  = threadIdx.x;
    const int lane = tid & 31;
    const int warp = tid >> 5;
    __shared__ float red[8];

    float4 u0 = *reinterpret_cast<const float4*>(&p[tid * 8]);
    float4 u1 = *reinterpret_cast<const float4*>(&p[tid * 8 + 4]);
    float v[8] = {u0.x, u0.y, u0.z, u0.w, u1.x, u1.y, u1.z, u1.w};

    float m = v[0];
#pragma unroll
    for (int i = 1; i < 8; i++) m = fmaxf(m, v[i]);
#pragma unroll
    for (int o = 16; o > 0; o >>= 1) m = fmaxf(m, __shfl_xor_sync(0xffffffffu, m, o));
    if (lane == 0) red[warp] = m;
    __syncthreads();
    m = red[0];
#pragma unroll
    for (int i = 1; i < 8; i++) m = fmaxf(m, red[i]);
    __syncthreads();

    float s = 0.0f;
#pragma unroll
    for (int i = 0; i < 8; i++) { v[i] = __expf(v[i] - m); s += v[i]; }
#pragma unroll
    for (int o = 16; o > 0; o >>= 1) s += __shfl_xor_sync(0xffffffffu, s, o);
    if (lane == 0) red[warp] = s;
    __syncthreads();
    s = red[0];
#pragma unroll
    for (int i = 1; i < 8; i++) s += red[i];

    float inv = __frcp_rn(s);
    float4 w0, w1;
    w0.x = v[0] * inv; w0.y = v[1] * inv; w0.z = v[2] * inv; w0.w = v[3] * inv;
    w1.x = v[4] * inv; w1.y = v[5] * inv; w1.z = v[6] * inv; w1.w = v[7] * inv;
    *reinterpret_cast<float4*>(&p[tid * 8])     = w0;
    *reinterpret_cast<float4*>(&p[tid * 8 + 4]) = w1;
}

// ---------------------------------------------------------------------------
extern "C" void kernel_launch(void* const* d_in, const int* in_sizes, int n_in,
                              void* d_out, int out_size)
{
    const float* x  = (const float*)d_in[0];
    const float* Wq = (const float*)d_in[1];
    const float* Wk = (const float*)d_in[2];
    const float* Wv = (const float*)d_in[3];
    float* out = (float*)d_out;

    float *QKV, *Vt, *S, *WT;
    cudaGetSymbolAddress((void**)&QKV, g_QKV);
    cudaGetSymbolAddress((void**)&Vt,  g_Vt);
    cudaGetSymbolAddress((void**)&S,   g_S);
    cudaGetSymbolAddress((void**)&WT,  g_WT);

    cudaFuncSetAttribute(tc_gemm7, cudaFuncAttributeMaxDynamicSharedMemorySize, SMEMB);

    const dim3 gemmBlk(256);
    const dim3 blk256(256);
    const dim3 tblk(32, 8);
    const int M_proj = BATCH * SEQ;  // 16384

    // 1) Transpose weights into concat WT [1536, 512] (K-major rows)
    {
        dim3 g(DIM / 32, DIM / 32, 1);
        transpose_kernel<<<g, tblk>>>(Wq, WT + 0L * DIM * DIM, DIM, DIM, 0, 0);
        transpose_kernel<<<g, tblk>>>(Wk, WT + 1L * DIM * DIM, DIM, DIM, 0, 0);
        transpose_kernel<<<g, tblk>>>(Wv, WT + 2L * DIM * DIM, DIM, DIM, 0, 0);
    }

    // 2) Fused QKV projection: QKV[16384,1536] = x[16384,512] @ WT^T
    {
        dim3 g(NQKV / 128, M_proj / 128, 1);
        tc_gemm7<<<g, gemmBlk, SMEMB>>>(x, WT, QKV, M_proj, NQKV, DIM,
                                        DIM, DIM, NQKV, 0, 0, 0, 1.0f);
    }

    // 3) Transpose V (QKV cols 1024..1535) per batch -> Vt [512, 2048]
    {
        dim3 g(DIM / 32, SEQ / 32, BATCH);
        transpose_kernel<<<g, tblk>>>(QKV + 2 * DIM, Vt, SEQ, NQKV,
                                      (long)SEQ * NQKV, (long)DIM * SEQ);
    }

    // 4) Scores: S[b] = Q[b] @ K[b]^T / sqrt(D)
    {
        const float scale = 0.044194173824159216f;  // 1/sqrt(512)
        dim3 g(SEQ / 128, SEQ / 128, BATCH);
        tc_gemm7<<<g, gemmBlk, SMEMB>>>(QKV, QKV + DIM, S, SEQ, SEQ, DIM,
                                        NQKV, NQKV, SEQ,
                                        (long)SEQ * NQKV, (long)SEQ * NQKV,
                                        (long)SEQ * SEQ, scale);
    }

    // 5) Softmax rows (in place)
    softmax_kernel<<<BATCH * SEQ, blk256>>>(S);

    // 6) out[b] = P[b] @ Vt[b]^T
    {
        dim3 g(DIM / 128, SEQ / 128, BATCH);
        tc_gemm7<<<g, gemmBlk, SMEMB>>>(S, Vt, out, SEQ, DIM, SEQ,
                                        SEQ, SEQ, DIM,
                                        (long)SEQ * SEQ, (long)DIM * SEQ,
                                        (long)SEQ * DIM, 1.0f);
    }
}

// round 11
// speedup vs baseline: 1.2563x; 1.2563x over previous
#include <cuda_runtime.h>
#include <cuda_bf16.h>
#include <cstdint>

#define BATCH 8
#define SEQ   2048
#define DIM   512
#define NQKV  1536   // 3*DIM

// ---------------------------------------------------------------------------
// Scratch (device globals)
// ---------------------------------------------------------------------------
__device__ __align__(16) float g_QKV[(long)BATCH * SEQ * NQKV];  // 96 MB
__device__ __align__(16) float g_Vt [(long)BATCH * DIM * SEQ];   // 32 MB
__device__ __align__(16) float g_S  [(long)BATCH * SEQ * SEQ];   // 128 MB
__device__ __align__(16) float g_WT [(long)NQKV * DIM];          // 3 MB

// ---------------------------------------------------------------------------
// PTX helpers (baseline ISA: ldmatrix + mma.sync, sm_80+)
// ---------------------------------------------------------------------------
__device__ __forceinline__ uint32_t smem_u32(const void* p) {
    uint32_t a;
    asm("{ .reg .u64 t; cvta.to.shared.u64 t, %1; cvt.u32.u64 %0, t; }"
        : "=r"(a) : "l"(p));
    return a;
}
__device__ __forceinline__ void ldsm_x4(uint32_t addr, uint32_t* r) {
    asm volatile("ldmatrix.sync.aligned.m8n8.x4.shared.b16 {%0,%1,%2,%3}, [%4];"
                 : "=r"(r[0]), "=r"(r[1]), "=r"(r[2]), "=r"(r[3]) : "r"(addr));
}
__device__ __forceinline__ void mma_bf16(float* c, const uint32_t* a, const uint32_t* b) {
    asm volatile(
        "mma.sync.aligned.m16n8k16.row.col.f32.bf16.bf16.f32 "
        "{%0,%1,%2,%3}, {%4,%5,%6,%7}, {%8,%9}, {%0,%1,%2,%3};"
        : "+f"(c[0]), "+f"(c[1]), "+f"(c[2]), "+f"(c[3])
        : "r"(a[0]), "r"(a[1]), "r"(a[2]), "r"(a[3]), "r"(b[0]), "r"(b[1]));
}

// Convert float4 -> hi/lo bf16 pairs and store 8B each to smem
__device__ __forceinline__ void cvt_store(char* hi, char* lo, uint32_t off, float4 v) {
    __nv_bfloat162 h01 = __floats2bfloat162_rn(v.x, v.y);
    __nv_bfloat162 h23 = __floats2bfloat162_rn(v.z, v.w);
    __nv_bfloat162 l01 = __floats2bfloat162_rn(v.x - __bfloat162float(h01.x),
                                               v.y - __bfloat162float(h01.y));
    __nv_bfloat162 l23 = __floats2bfloat162_rn(v.z - __bfloat162float(h23.x),
                                               v.w - __bfloat162float(h23.y));
    *reinterpret_cast<uint2*>(hi + off) =
        make_uint2(*reinterpret_cast<uint32_t*>(&h01), *reinterpret_cast<uint32_t*>(&h23));
    *reinterpret_cast<uint2*>(lo + off) =
        make_uint2(*reinterpret_cast<uint32_t*>(&l01), *reinterpret_cast<uint32_t*>(&l23));
}

// ---------------------------------------------------------------------------
// Tensor-core GEMM: C[M,N] = alpha * A[M,K] @ B[N,K]^T  (fp32 in/out)
// In-kernel split precision (hi+lo bf16). CTA tile 128x128, K-CHUNK 64,
// double-buffered smem, 1 sync per chunk. 512 threads / 16 warps, 32x32
// warp tiles. TERM-MAJOR MMA order: all hi*hi, then hi*lo, then lo*hi —
// same-accumulator reuse distance 8 MMAs, so no RAW latency stalls.
// ---------------------------------------------------------------------------
#define KC     64
#define ROWB   144                 // 64 bf16 = 128B + 16B pad: conflict-free ldsm
#define TILEB  (128 * ROWB)        // 18432
#define STAGEB (4 * TILEB)         // Ahi, Alo, Bhi, Blo = 73728
#define SMEMB  (2 * STAGEB)        // 147456

__global__ __launch_bounds__(512, 1)
void tc_gemm8(const float* __restrict__ A, const float* __restrict__ B,
              float* __restrict__ C, int M, int N, int K,
              int ldA, int ldB, int ldC, long sA, long sB, long sC, float alpha)
{
    extern __shared__ __align__(16) char smem[];

    const long zb = blockIdx.z;
    A += zb * sA;
    B += zb * sB;
    C += zb * sC;

    const int tid  = threadIdx.x;
    const int wid  = tid >> 5;
    const int lane = tid & 31;
    const int wm   = wid & 3;   // 4 warps along M (32 rows each)
    const int wn   = wid >> 2;  // 4 warps along N (32 cols each)

    const int rowA = blockIdx.y * 128;
    const int rowB = blockIdx.x * 128;

    // Loader mapping: 64-float rows; 16 threads per row; 4 row-iterations
    const int lrow = tid >> 4;        // 0..31, advance by 32 per i
    const int lc4  = tid & 15;        // float4 index within row

    // ldmatrix lane selectors
    const int aRow = lane & 15;
    const int aK   = (lane >> 4) * 8;
    const int bRow = (lane & 7) + ((lane >> 4) & 1) * 8;
    const int bK   = ((lane >> 3) & 1) * 8;

    float acc[2][4][4];
#pragma unroll
    for (int i = 0; i < 2; i++)
#pragma unroll
        for (int j = 0; j < 4; j++)
#pragma unroll
            for (int k = 0; k < 4; k++) acc[i][j][k] = 0.0f;

    const int nchunk = K / KC;
    float4 sa[4], sb[4];

    auto prefetch = [&](int c) {
        const int kb = c * KC;
#pragma unroll
        for (int i = 0; i < 4; i++) {
            const int r = lrow + i * 32;
            sa[i] = *reinterpret_cast<const float4*>(&A[(long)(rowA + r) * ldA + kb + lc4 * 4]);
            sb[i] = *reinterpret_cast<const float4*>(&B[(long)(rowB + r) * ldB + kb + lc4 * 4]);
        }
    };

    auto cvtstore = [&](int st) {
        char* base = smem + st * STAGEB;
#pragma unroll
        for (int i = 0; i < 4; i++) {
            const int r = lrow + i * 32;
            const uint32_t off = (uint32_t)(r * ROWB + lc4 * 8);
            cvt_store(base + 0 * TILEB, base + 1 * TILEB, off, sa[i]);
            cvt_store(base + 2 * TILEB, base + 3 * TILEB, off, sb[i]);
        }
    };

    prefetch(0);
    cvtstore(0);
    __syncthreads();

    const uint32_t sbase = smem_u32(smem);

    for (int c = 0; c < nchunk; c++) {
        const int st = c & 1;

        if (c + 1 < nchunk) prefetch(c + 1);   // LDG latency hides under MMA

        const uint32_t uA  = sbase + st * STAGEB;
        const uint32_t uAl = uA + TILEB;
        const uint32_t uB  = uA + 2 * TILEB;
        const uint32_t uBl = uA + 3 * TILEB;

#pragma unroll
        for (int ks = 0; ks < 4; ks++) {            // 4 k16 steps per 64-chunk
            uint32_t ah[2][4], al[2][4], bh[4][2], bl[4][2];
#pragma unroll
            for (int mi = 0; mi < 2; mi++) {
                const uint32_t off = (uint32_t)((wm * 32 + mi * 16 + aRow) * ROWB
                                                + (ks * 16 + aK) * 2);
                ldsm_x4(uA + off, ah[mi]);
                ldsm_x4(uAl + off, al[mi]);
            }
#pragma unroll
            for (int nj = 0; nj < 2; nj++) {
                const uint32_t off = (uint32_t)((wn * 32 + nj * 16 + bRow) * ROWB
                                                + (ks * 16 + bK) * 2);
                uint32_t rh[4], rl[4];
                ldsm_x4(uB + off, rh);
                ldsm_x4(uBl + off, rl);
                bh[nj * 2][0] = rh[0]; bh[nj * 2][1] = rh[1];
                bh[nj * 2 + 1][0] = rh[2]; bh[nj * 2 + 1][1] = rh[3];
                bl[nj * 2][0] = rl[0]; bl[nj * 2][1] = rl[1];
                bl[nj * 2 + 1][0] = rl[2]; bl[nj * 2 + 1][1] = rl[3];
            }
            // TERM-MAJOR: 8 independent accumulators between same-acc reuse
#pragma unroll
            for (int mi = 0; mi < 2; mi++)
#pragma unroll
                for (int ni = 0; ni < 4; ni++)
                    mma_bf16(acc[mi][ni], ah[mi], bh[ni]);   // hi*hi
#pragma unroll
            for (int mi = 0; mi < 2; mi++)
#pragma unroll
                for (int ni = 0; ni < 4; ni++)
                    mma_bf16(acc[mi][ni], ah[mi], bl[ni]);   // hi*lo
#pragma unroll
            for (int mi = 0; mi < 2; mi++)
#pragma unroll
                for (int ni = 0; ni < 4; ni++)
                    mma_bf16(acc[mi][ni], al[mi], bh[ni]);   // lo*hi
        }

        if (c + 1 < nchunk) cvtstore(st ^ 1);  // overlaps with tail of MMA stream
        __syncthreads();
    }

    // Epilogue (fp32)
    const int g = lane >> 2, t = lane & 3;
#pragma unroll
    for (int mi = 0; mi < 2; mi++) {
#pragma unroll
        for (int half = 0; half < 2; half++) {
            const long r = (long)(rowA + wm * 32 + mi * 16 + g + half * 8);
#pragma unroll
            for (int ni = 0; ni < 4; ni++) {
                const int col = rowB + wn * 32 + ni * 8 + t * 2;
                *reinterpret_cast<float2*>(&C[r * ldC + col]) =
                    make_float2(acc[mi][ni][half * 2 + 0] * alpha,
                                acc[mi][ni][half * 2 + 1] * alpha);
            }
        }
    }
}

// ---------------------------------------------------------------------------
// Transpose: out[c,r] = in[r,c]; input ld = ldIn, output ld = R; batched via z
// ---------------------------------------------------------------------------
__global__ __launch_bounds__(256)
void transpose_kernel(const float* __restrict__ in, float* __restrict__ out,
                      int R, int ldIn, long sIn, long sOut)
{
    __shared__ float t[32][33];
    in  += (long)blockIdx.z * sIn;
    out += (long)blockIdx.z * sOut;
    const int rb = blockIdx.y * 32, cb = blockIdx.x * 32;
    const int x = threadIdx.x, y = threadIdx.y;  // 32 x 8
#pragma unroll
    for (int j = 0; j < 32; j += 8)
        t[y + j][x] = in[(long)(rb + y + j) * ldIn + cb + x];
    __syncthreads();
#pragma unroll
    for (int j = 0; j < 32; j += 8)
        out[(long)(cb + y + j) * R + rb + x] = t[x][y + j];
}

// ---------------------------------------------------------------------------
// Row softmax over SEQ=2048 columns, in-place fp32. One 256-thread CTA/row.
// ---------------------------------------------------------------------------
__global__ __launch_bounds__(256)
void softmax_kernel(float* __restrict__ S)
{
    float* p = S + (long)blockIdx.x * SEQ;
    const int tid  = threadIdx.x;
    const int lane = tid & 31;
    const int warp = tid >> 5;
    __shared__ float red[8];

    float4 u0 = *reinterpret_cast<const float4*>(&p[tid * 8]);
    float4 u1 = *reinterpret_cast<const float4*>(&p[tid * 8 + 4]);
    float v[8] = {u0.x, u0.y, u0.z, u0.w, u1.x, u1.y, u1.z, u1.w};

    float m = v[0];
#pragma unroll
    for (int i = 1; i < 8; i++) m = fmaxf(m, v[i]);
#pragma unroll
    for (int o = 16; o > 0; o >>= 1) m = fmaxf(m, __shfl_xor_sync(0xffffffffu, m, o));
    if (lane == 0) red[warp] = m;
    __syncthreads();
    m = red[0];
#pragma unroll
    for (int i = 1; i < 8; i++) m = fmaxf(m, red[i]);
    __syncthreads();

    float s = 0.0f;
#pragma unroll
    for (int i = 0; i < 8; i++) { v[i] = __expf(v[i] - m); s += v[i]; }
#pragma unroll
    for (int o = 16; o > 0; o >>= 1) s += __shfl_xor_sync(0xffffffffu, s, o);
    if (lane == 0) red[warp] = s;
    __syncthreads();
    s = red[0];
#pragma unroll
    for (int i = 1; i < 8; i++) s += red[i];

    float inv = __frcp_rn(s);
    float4 w0, w1;
    w0.x = v[0] * inv; w0.y = v[1] * inv; w0.z = v[2] * inv; w0.w = v[3] * inv;
    w1.x = v[4] * inv; w1.y = v[5] * inv; w1.z = v[6] * inv; w1.w = v[7] * inv;
    *reinterpret_cast<float4*>(&p[tid * 8])     = w0;
    *reinterpret_cast<float4*>(&p[tid * 8 + 4]) = w1;
}

// ---------------------------------------------------------------------------
extern "C" void kernel_launch(void* const* d_in, const int* in_sizes, int n_in,
                              void* d_out, int out_size)
{
    const float* x  = (const float*)d_in[0];
    const float* Wq = (const float*)d_in[1];
    const float* Wk = (const float*)d_in[2];
    const float* Wv = (const float*)d_in[3];
    float* out = (float*)d_out;

    float *QKV, *Vt, *S, *WT;
    cudaGetSymbolAddress((void**)&QKV, g_QKV);
    cudaGetSymbolAddress((void**)&Vt,  g_Vt);
    cudaGetSymbolAddress((void**)&S,   g_S);
    cudaGetSymbolAddress((void**)&WT,  g_WT);

    cudaFuncSetAttribute(tc_gemm8, cudaFuncAttributeMaxDynamicSharedMemorySize, SMEMB);

    const dim3 gemmBlk(512);   // tc_gemm8 only
    const dim3 blk256(256);    // softmax
    const dim3 tblk(32, 8);    // transpose
    const int M_proj = BATCH * SEQ;  // 16384

    // 1) Transpose weights into concat WT [1536, 512] (K-major rows)
    {
        dim3 g(DIM / 32, DIM / 32, 1);
        transpose_kernel<<<g, tblk>>>(Wq, WT + 0L * DIM * DIM, DIM, DIM, 0, 0);
        transpose_kernel<<<g, tblk>>>(Wk, WT + 1L * DIM * DIM, DIM, DIM, 0, 0);
        transpose_kernel<<<g, tblk>>>(Wv, WT + 2L * DIM * DIM, DIM, DIM, 0, 0);
    }

    // 2) Fused QKV projection: QKV[16384,1536] = x[16384,512] @ WT^T
    {
        dim3 g(NQKV / 128, M_proj / 128, 1);
        tc_gemm8<<<g, gemmBlk, SMEMB>>>(x, WT, QKV, M_proj, NQKV, DIM,
                                        DIM, DIM, NQKV, 0, 0, 0, 1.0f);
    }

    // 3) Transpose V (QKV cols 1024..1535) per batch -> Vt [512, 2048]
    {
        dim3 g(DIM / 32, SEQ / 32, BATCH);
        transpose_kernel<<<g, tblk>>>(QKV + 2 * DIM, Vt, SEQ, NQKV,
                                      (long)SEQ * NQKV, (long)DIM * SEQ);
    }

    // 4) Scores: S[b] = Q[b] @ K[b]^T / sqrt(D)
    {
        const float scale = 0.044194173824159216f;  // 1/sqrt(512)
        dim3 g(SEQ / 128, SEQ / 128, BATCH);
        tc_gemm8<<<g, gemmBlk, SMEMB>>>(QKV, QKV + DIM, S, SEQ, SEQ, DIM,
                                        NQKV, NQKV, SEQ,
                                        (long)SEQ * NQKV, (long)SEQ * NQKV,
                                        (long)SEQ * SEQ, scale);
    }

    // 5) Softmax rows (in place)
    softmax_kernel<<<BATCH * SEQ, blk256>>>(S);

    // 6) out[b] = P[b] @ Vt[b]^T
    {
        dim3 g(DIM / 128, SEQ / 128, BATCH);
        tc_gemm8<<<g, gemmBlk, SMEMB>>>(S, Vt, out, SEQ, DIM, SEQ,
                                        SEQ, SEQ, DIM,
                                        (long)SEQ * SEQ, (long)DIM * SEQ,
                                        (long)SEQ * DIM, 1.0f);
    }
}

// round 12
// speedup vs baseline: 1.3307x; 1.0592x over previous
#include <cuda_runtime.h>
#include <cuda_bf16.h>
#include <cstdint>

#define BATCH 8
#define SEQ   2048
#define DIM   512
#define NQKV  1536   // 3*DIM

// ---------------------------------------------------------------------------
// Scratch (device globals)
// ---------------------------------------------------------------------------
__device__ __align__(16) float g_QKV[(long)BATCH * SEQ * NQKV];  // 96 MB
__device__ __align__(16) float g_Vt [(long)BATCH * DIM * SEQ];   // 32 MB
__device__ __align__(16) float g_S  [(long)BATCH * SEQ * SEQ];   // 128 MB
__device__ __align__(16) float g_WT [(long)NQKV * DIM];          // 3 MB

// ---------------------------------------------------------------------------
// PTX helpers (baseline ISA: ldmatrix + mma.sync, sm_80+)
// ---------------------------------------------------------------------------
__device__ __forceinline__ uint32_t smem_u32(const void* p) {
    uint32_t a;
    asm("{ .reg .u64 t; cvta.to.shared.u64 t, %1; cvt.u32.u64 %0, t; }"
        : "=r"(a) : "l"(p));
    return a;
}
__device__ __forceinline__ void ldsm_x4(uint32_t addr, uint32_t* r) {
    asm volatile("ldmatrix.sync.aligned.m8n8.x4.shared.b16 {%0,%1,%2,%3}, [%4];"
                 : "=r"(r[0]), "=r"(r[1]), "=r"(r[2]), "=r"(r[3]) : "r"(addr));
}
__device__ __forceinline__ void mma_bf16(float* c, const uint32_t* a, const uint32_t* b) {
    asm volatile(
        "mma.sync.aligned.m16n8k16.row.col.f32.bf16.bf16.f32 "
        "{%0,%1,%2,%3}, {%4,%5,%6,%7}, {%8,%9}, {%0,%1,%2,%3};"
        : "+f"(c[0]), "+f"(c[1]), "+f"(c[2]), "+f"(c[3])
        : "r"(a[0]), "r"(a[1]), "r"(a[2]), "r"(a[3]), "r"(b[0]), "r"(b[1]));
}

// Convert 8 consecutive floats -> 16B hi + 16B lo bf16, store to smem
__device__ __forceinline__ void cvt_store16(char* hi, char* lo, uint32_t off,
                                            float4 v0, float4 v1) {
    __nv_bfloat162 h[4], l[4];
    h[0] = __floats2bfloat162_rn(v0.x, v0.y);
    h[1] = __floats2bfloat162_rn(v0.z, v0.w);
    h[2] = __floats2bfloat162_rn(v1.x, v1.y);
    h[3] = __floats2bfloat162_rn(v1.z, v1.w);
    l[0] = __floats2bfloat162_rn(v0.x - __bfloat162float(h[0].x),
                                 v0.y - __bfloat162float(h[0].y));
    l[1] = __floats2bfloat162_rn(v0.z - __bfloat162float(h[1].x),
                                 v0.w - __bfloat162float(h[1].y));
    l[2] = __floats2bfloat162_rn(v1.x - __bfloat162float(h[2].x),
                                 v1.y - __bfloat162float(h[2].y));
    l[3] = __floats2bfloat162_rn(v1.z - __bfloat162float(h[3].x),
                                 v1.w - __bfloat162float(h[3].y));
    *reinterpret_cast<uint4*>(hi + off) = *reinterpret_cast<uint4*>(h);
    *reinterpret_cast<uint4*>(lo + off) = *reinterpret_cast<uint4*>(l);
}

// ---------------------------------------------------------------------------
// Tensor-core GEMM, WARP-SPECIALIZED: C[M,N] = alpha * A[M,K] @ B[N,K]^T
// In-kernel split precision (hi+lo bf16, 3 MMA terms). CTA tile 128x128,
// K-chunk 64, double-buffered smem, 1 sync per chunk.
// 512 threads: warps 0-7 CONSUMERS (2M x 4N grid of 64x32 tiles; only
// ldsm+MMA, hit barrier right after last MMA), warps 8-15 PRODUCERS
// (LDG fp32 -> hi/lo split -> STS.128 into the next stage, concurrent with
// the consumer MMA window). Removes the per-warp cvt/STS tail that was
// exposing ~2000 cyc/chunk in R5-R11.
// ---------------------------------------------------------------------------
#define KC     64
#define ROWB   144                 // 64 bf16 = 128B + 16B pad: conflict-free ldsm
#define TILEB  (128 * ROWB)        // 18432
#define STAGEB (4 * TILEB)         // Ahi, Alo, Bhi, Blo = 73728
#define SMEMB  (2 * STAGEB)        // 147456

__global__ __launch_bounds__(512, 1)
void tc_gemm9(const float* __restrict__ A, const float* __restrict__ B,
              float* __restrict__ C, int M, int N, int K,
              int ldA, int ldB, int ldC, long sA, long sB, long sC, float alpha)
{
    extern __shared__ __align__(16) char smem[];
    const uint32_t sbase = smem_u32(smem);

    const long zb = blockIdx.z;
    A += zb * sA;
    B += zb * sB;
    C += zb * sC;

    const int tid  = threadIdx.x;
    const int wid  = tid >> 5;
    const int lane = tid & 31;
    const bool consumer = (wid < 8);

    const int rowA = blockIdx.y * 128;
    const int rowB = blockIdx.x * 128;
    const int nchunk = K / KC;

    // ---- consumer state ----
    const int wm = wid & 1;    // 2 warps along M (64 rows each)
    const int wn = wid >> 1;   // 4 warps along N (32 cols each)  [wid<8]
    const int aRow = lane & 15;
    const int aK   = (lane >> 4) * 8;
    const int bRow = (lane & 7) + ((lane >> 4) & 1) * 8;
    const int bK   = ((lane >> 3) & 1) * 8;

    float acc[4][4][4];
#pragma unroll
    for (int i = 0; i < 4; i++)
#pragma unroll
        for (int j = 0; j < 4; j++)
#pragma unroll
            for (int k = 0; k < 4; k++) acc[i][j][k] = 0.0f;

    // ---- producer state ----
    const int ptid = tid - 256;        // 0..255 for producers
    const int prow = ptid >> 3;        // 0..31 (row, advance by 32 per i)
    const int pseg = ptid & 7;         // 8-float k-segment within 64

    // Producer: load+split chunk c into stage st
    auto produce = [&](int st, int c) {
        const int kb = c * KC;
        char* base = smem + st * STAGEB;
#pragma unroll
        for (int i = 0; i < 4; i++) {
            const int r = prow + i * 32;
            const uint32_t off = (uint32_t)(r * ROWB + pseg * 16);
            {
                const float* p = &A[(long)(rowA + r) * ldA + kb + pseg * 8];
                float4 v0 = *reinterpret_cast<const float4*>(p);
                float4 v1 = *reinterpret_cast<const float4*>(p + 4);
                cvt_store16(base + 0 * TILEB, base + 1 * TILEB, off, v0, v1);
            }
            {
                const float* p = &B[(long)(rowB + r) * ldB + kb + pseg * 8];
                float4 v0 = *reinterpret_cast<const float4*>(p);
                float4 v1 = *reinterpret_cast<const float4*>(p + 4);
                cvt_store16(base + 2 * TILEB, base + 3 * TILEB, off, v0, v1);
            }
        }
    };

    // Consumer: MMA over stage st
    auto compute = [&](int st) {
        const uint32_t uA  = sbase + st * STAGEB;
        const uint32_t uAl = uA + TILEB;
        const uint32_t uB  = uA + 2 * TILEB;
        const uint32_t uBl = uA + 3 * TILEB;
#pragma unroll
        for (int ks = 0; ks < 4; ks++) {
            uint32_t bh[4][2], bl[4][2];
#pragma unroll
            for (int nj = 0; nj < 2; nj++) {
                const uint32_t off = (uint32_t)((wn * 32 + nj * 16 + bRow) * ROWB
                                                + (ks * 16 + bK) * 2);
                uint32_t rh[4], rl[4];
                ldsm_x4(uB + off, rh);
                ldsm_x4(uBl + off, rl);
                bh[nj * 2][0] = rh[0]; bh[nj * 2][1] = rh[1];
                bh[nj * 2 + 1][0] = rh[2]; bh[nj * 2 + 1][1] = rh[3];
                bl[nj * 2][0] = rl[0]; bl[nj * 2][1] = rl[1];
                bl[nj * 2 + 1][0] = rl[2]; bl[nj * 2 + 1][1] = rl[3];
            }
#pragma unroll
            for (int mi = 0; mi < 4; mi++) {
                uint32_t ah[4], al[4];
                const uint32_t off = (uint32_t)((wm * 64 + mi * 16 + aRow) * ROWB
                                                + (ks * 16 + aK) * 2);
                ldsm_x4(uA + off, ah);
                ldsm_x4(uAl + off, al);
#pragma unroll
                for (int ni = 0; ni < 4; ni++) {
                    mma_bf16(acc[mi][ni], ah, bh[ni]);
                    mma_bf16(acc[mi][ni], ah, bl[ni]);
                    mma_bf16(acc[mi][ni], al, bh[ni]);
                }
            }
        }
    };

    // Prologue: producers fill stage 0
    if (!consumer) produce(0, 0);
    __syncthreads();

    for (int c = 0; c < nchunk; c++) {
        if (consumer) {
            compute(c & 1);
        } else if (c + 1 < nchunk) {
            produce((c + 1) & 1, c + 1);   // runs under the MMA window
        }
        __syncthreads();
    }

    // Epilogue (consumers only; no further syncs)
    if (consumer) {
        const int g = lane >> 2, t = lane & 3;
#pragma unroll
        for (int mi = 0; mi < 4; mi++) {
#pragma unroll
            for (int half = 0; half < 2; half++) {
                const long r = (long)(rowA + wm * 64 + mi * 16 + g + half * 8);
#pragma unroll
                for (int ni = 0; ni < 4; ni++) {
                    const int col = rowB + wn * 32 + ni * 8 + t * 2;
                    *reinterpret_cast<float2*>(&C[r * ldC + col]) =
                        make_float2(acc[mi][ni][half * 2 + 0] * alpha,
                                    acc[mi][ni][half * 2 + 1] * alpha);
                }
            }
        }
    }
}

// ---------------------------------------------------------------------------
// Transpose: out[c,r] = in[r,c]; input ld = ldIn, output ld = R; batched via z
// ---------------------------------------------------------------------------
__global__ __launch_bounds__(256)
void transpose_kernel(const float* __restrict__ in, float* __restrict__ out,
                      int R, int ldIn, long sIn, long sOut)
{
    __shared__ float t[32][33];
    in  += (long)blockIdx.z * sIn;
    out += (long)blockIdx.z * sOut;
    const int rb = blockIdx.y * 32, cb = blockIdx.x * 32;
    const int x = threadIdx.x, y = threadIdx.y;  // 32 x 8
#pragma unroll
    for (int j = 0; j < 32; j += 8)
        t[y + j][x] = in[(long)(rb + y + j) * ldIn + cb + x];
    __syncthreads();
#pragma unroll
    for (int j = 0; j < 32; j += 8)
        out[(long)(cb + y + j) * R + rb + x] = t[x][y + j];
}

// ---------------------------------------------------------------------------
// Row softmax over SEQ=2048 columns, in-place fp32. One 256-thread CTA/row.
// ---------------------------------------------------------------------------
__global__ __launch_bounds__(256)
void softmax_kernel(float* __restrict__ S)
{
    float* p = S + (long)blockIdx.x * SEQ;
    const int tid  = threadIdx.x;
    const int lane = tid & 31;
    const int warp = tid >> 5;
    __shared__ float red[8];

    float4 u0 = *reinterpret_cast<const float4*>(&p[tid * 8]);
    float4 u1 = *reinterpret_cast<const float4*>(&p[tid * 8 + 4]);
    float v[8] = {u0.x, u0.y, u0.z, u0.w, u1.x, u1.y, u1.z, u1.w};

    float m = v[0];
#pragma unroll
    for (int i = 1; i < 8; i++) m = fmaxf(m, v[i]);
#pragma unroll
    for (int o = 16; o > 0; o >>= 1) m = fmaxf(m, __shfl_xor_sync(0xffffffffu, m, o));
    if (lane == 0) red[warp] = m;
    __syncthreads();
    m = red[0];
#pragma unroll
    for (int i = 1; i < 8; i++) m = fmaxf(m, red[i]);
    __syncthreads();

    float s = 0.0f;
#pragma unroll
    for (int i = 0; i < 8; i++) { v[i] = __expf(v[i] - m); s += v[i]; }
#pragma unroll
    for (int o = 16; o > 0; o >>= 1) s += __shfl_xor_sync(0xffffffffu, s, o);
    if (lane == 0) red[warp] = s;
    __syncthreads();
    s = red[0];
#pragma unroll
    for (int i = 1; i < 8; i++) s += red[i];

    float inv = __frcp_rn(s);
    float4 w0, w1;
    w0.x = v[0] * inv; w0.y = v[1] * inv; w0.z = v[2] * inv; w0.w = v[3] * inv;
    w1.x = v[4] * inv; w1.y = v[5] * inv; w1.z = v[6] * inv; w1.w = v[7] * inv;
    *reinterpret_cast<float4*>(&p[tid * 8])     = w0;
    *reinterpret_cast<float4*>(&p[tid * 8 + 4]) = w1;
}

// ---------------------------------------------------------------------------
extern "C" void kernel_launch(void* const* d_in, const int* in_sizes, int n_in,
                              void* d_out, int out_size)
{
    const float* x  = (const float*)d_in[0];
    const float* Wq = (const float*)d_in[1];
    const float* Wk = (const float*)d_in[2];
    const float* Wv = (const float*)d_in[3];
    float* out = (float*)d_out;

    float *QKV, *Vt, *S, *WT;
    cudaGetSymbolAddress((void**)&QKV, g_QKV);
    cudaGetSymbolAddress((void**)&Vt,  g_Vt);
    cudaGetSymbolAddress((void**)&S,   g_S);
    cudaGetSymbolAddress((void**)&WT,  g_WT);

    cudaFuncSetAttribute(tc_gemm9, cudaFuncAttributeMaxDynamicSharedMemorySize, SMEMB);

    const dim3 gemmBlk(512);   // tc_gemm9 only
    const dim3 blk256(256);    // softmax
    const dim3 tblk(32, 8);    // transpose
    const int M_proj = BATCH * SEQ;  // 16384

    // 1) Transpose weights into concat WT [1536, 512] (K-major rows)
    {
        dim3 g(DIM / 32, DIM / 32, 1);
        transpose_kernel<<<g, tblk>>>(Wq, WT + 0L * DIM * DIM, DIM, DIM, 0, 0);
        transpose_kernel<<<g, tblk>>>(Wk, WT + 1L * DIM * DIM, DIM, DIM, 0, 0);
        transpose_kernel<<<g, tblk>>>(Wv, WT + 2L * DIM * DIM, DIM, DIM, 0, 0);
    }

    // 2) Fused QKV projection: QKV[16384,1536] = x[16384,512] @ WT^T
    {
        dim3 g(NQKV / 128, M_proj / 128, 1);
        tc_gemm9<<<g, gemmBlk, SMEMB>>>(x, WT, QKV, M_proj, NQKV, DIM,
                                        DIM, DIM, NQKV, 0, 0, 0, 1.0f);
    }

    // 3) Transpose V (QKV cols 1024..1535) per batch -> Vt [512, 2048]
    {
        dim3 g(DIM / 32, SEQ / 32, BATCH);
        transpose_kernel<<<g, tblk>>>(QKV + 2 * DIM, Vt, SEQ, NQKV,
                                      (long)SEQ * NQKV, (long)DIM * SEQ);
    }

    // 4) Scores: S[b] = Q[b] @ K[b]^T / sqrt(D)
    {
        const float scale = 0.044194173824159216f;  // 1/sqrt(512)
        dim3 g(SEQ / 128, SEQ / 128, BATCH);
        tc_gemm9<<<g, gemmBlk, SMEMB>>>(QKV, QKV + DIM, S, SEQ, SEQ, DIM,
                                        NQKV, NQKV, SEQ,
                                        (long)SEQ * NQKV, (long)SEQ * NQKV,
                                        (long)SEQ * SEQ, scale);
    }

    // 5) Softmax rows (in place)
    softmax_kernel<<<BATCH * SEQ, blk256>>>(S);

    // 6) out[b] = P[b] @ Vt[b]^T
    {
        dim3 g(DIM / 128, SEQ / 128, BATCH);
        tc_gemm9<<<g, gemmBlk, SMEMB>>>(S, Vt, out, SEQ, DIM, SEQ,
                                        SEQ, SEQ, DIM,
                                        (long)SEQ * SEQ, (long)DIM * SEQ,
                                        (long)SEQ * DIM, 1.0f);
    }
}

// round 13
// speedup vs baseline: 1.3327x; 1.0015x over previous
#include <cuda_runtime.h>
#include <cuda_bf16.h>
#include <cstdint>

#define BATCH 8
#define SEQ   2048
#define DIM   512
#define NQKV  1536   // 3*DIM

// ---------------------------------------------------------------------------
// Scratch (device globals)
// ---------------------------------------------------------------------------
__device__ __align__(16) float g_QKV[(long)BATCH * SEQ * NQKV];  // 96 MB
__device__ __align__(16) float g_Vt [(long)BATCH * DIM * SEQ];   // 32 MB
__device__ __align__(16) float g_S  [(long)BATCH * SEQ * SEQ];   // 128 MB
__device__ __align__(16) float g_WT [(long)NQKV * DIM];          // 3 MB

// ---------------------------------------------------------------------------
// PTX helpers (baseline ISA: ldmatrix + mma.sync, sm_80+)
// ---------------------------------------------------------------------------
__device__ __forceinline__ uint32_t smem_u32(const void* p) {
    uint32_t a;
    asm("{ .reg .u64 t; cvta.to.shared.u64 t, %1; cvt.u32.u64 %0, t; }"
        : "=r"(a) : "l"(p));
    return a;
}
__device__ __forceinline__ void ldsm_x4(uint32_t addr, uint32_t* r) {
    asm volatile("ldmatrix.sync.aligned.m8n8.x4.shared.b16 {%0,%1,%2,%3}, [%4];"
                 : "=r"(r[0]), "=r"(r[1]), "=r"(r[2]), "=r"(r[3]) : "r"(addr));
}
__device__ __forceinline__ void mma_bf16(float* c, const uint32_t* a, const uint32_t* b) {
    asm volatile(
        "mma.sync.aligned.m16n8k16.row.col.f32.bf16.bf16.f32 "
        "{%0,%1,%2,%3}, {%4,%5,%6,%7}, {%8,%9}, {%0,%1,%2,%3};"
        : "+f"(c[0]), "+f"(c[1]), "+f"(c[2]), "+f"(c[3])
        : "r"(a[0]), "r"(a[1]), "r"(a[2]), "r"(a[3]), "r"(b[0]), "r"(b[1]));
}

// Convert 8 consecutive floats -> 16B hi + 16B lo bf16, store to smem
__device__ __forceinline__ void cvt_store16(char* hi, char* lo, uint32_t off,
                                            float4 v0, float4 v1) {
    __nv_bfloat162 h[4], l[4];
    h[0] = __floats2bfloat162_rn(v0.x, v0.y);
    h[1] = __floats2bfloat162_rn(v0.z, v0.w);
    h[2] = __floats2bfloat162_rn(v1.x, v1.y);
    h[3] = __floats2bfloat162_rn(v1.z, v1.w);
    l[0] = __floats2bfloat162_rn(v0.x - __bfloat162float(h[0].x),
                                 v0.y - __bfloat162float(h[0].y));
    l[1] = __floats2bfloat162_rn(v0.z - __bfloat162float(h[1].x),
                                 v0.w - __bfloat162float(h[1].y));
    l[2] = __floats2bfloat162_rn(v1.x - __bfloat162float(h[2].x),
                                 v1.y - __bfloat162float(h[2].y));
    l[3] = __floats2bfloat162_rn(v1.z - __bfloat162float(h[3].x),
                                 v1.w - __bfloat162float(h[3].y));
    *reinterpret_cast<uint4*>(hi + off) = *reinterpret_cast<uint4*>(h);
    *reinterpret_cast<uint4*>(lo + off) = *reinterpret_cast<uint4*>(l);
}

// ---------------------------------------------------------------------------
// Tensor-core GEMM, WARP-SPECIALIZED + FRAGMENT-PIPELINED:
// C[M,N] = alpha * A[M,K] @ B[N,K]^T, in-kernel split precision
// (hi+lo bf16, 3 MMA terms). CTA tile 128x128, K-chunk 64, double-buffered
// smem, 1 sync per chunk. 512 threads: warps 0-7 consumers (2M x 4N of
// 64x32 tiles), warps 8-15 producers (LDG->split->STS for next stage).
// Consumer inner loop issues A-ldsm two mi-tiles ahead of their MMAs so
// every ldsm has >=48 cycles of cover — no per-mi LDS-latency stall.
// ---------------------------------------------------------------------------
#define KC     64
#define ROWB   144                 // 64 bf16 = 128B + 16B pad: conflict-free ldsm
#define TILEB  (128 * ROWB)        // 18432
#define STAGEB (4 * TILEB)         // Ahi, Alo, Bhi, Blo = 73728
#define SMEMB  (2 * STAGEB)        // 147456

__global__ __launch_bounds__(512, 1)
void tc_gemm10(const float* __restrict__ A, const float* __restrict__ B,
               float* __restrict__ C, int M, int N, int K,
               int ldA, int ldB, int ldC, long sA, long sB, long sC, float alpha)
{
    extern __shared__ __align__(16) char smem[];
    const uint32_t sbase = smem_u32(smem);

    const long zb = blockIdx.z;
    A += zb * sA;
    B += zb * sB;
    C += zb * sC;

    const int tid  = threadIdx.x;
    const int wid  = tid >> 5;
    const int lane = tid & 31;
    const bool consumer = (wid < 8);

    const int rowA = blockIdx.y * 128;
    const int rowB = blockIdx.x * 128;
    const int nchunk = K / KC;

    // ---- consumer state ----
    const int wm = wid & 1;    // 2 warps along M (64 rows each)
    const int wn = wid >> 1;   // 4 warps along N (32 cols each)  [wid<8]
    const int aRow = lane & 15;
    const int aK   = (lane >> 4) * 8;
    const int bRow = (lane & 7) + ((lane >> 4) & 1) * 8;
    const int bK   = ((lane >> 3) & 1) * 8;

    float acc[4][4][4];
#pragma unroll
    for (int i = 0; i < 4; i++)
#pragma unroll
        for (int j = 0; j < 4; j++)
#pragma unroll
            for (int k = 0; k < 4; k++) acc[i][j][k] = 0.0f;

    // ---- producer state ----
    const int ptid = tid - 256;        // 0..255 for producers
    const int prow = ptid >> 3;        // 0..31 (row, advance by 32 per i)
    const int pseg = ptid & 7;         // 8-float k-segment within 64

    auto produce = [&](int st, int c) {
        const int kb = c * KC;
        char* base = smem + st * STAGEB;
#pragma unroll
        for (int i = 0; i < 4; i++) {
            const int r = prow + i * 32;
            const uint32_t off = (uint32_t)(r * ROWB + pseg * 16);
            {
                const float* p = &A[(long)(rowA + r) * ldA + kb + pseg * 8];
                float4 v0 = *reinterpret_cast<const float4*>(p);
                float4 v1 = *reinterpret_cast<const float4*>(p + 4);
                cvt_store16(base + 0 * TILEB, base + 1 * TILEB, off, v0, v1);
            }
            {
                const float* p = &B[(long)(rowB + r) * ldB + kb + pseg * 8];
                float4 v0 = *reinterpret_cast<const float4*>(p);
                float4 v1 = *reinterpret_cast<const float4*>(p + 4);
                cvt_store16(base + 2 * TILEB, base + 3 * TILEB, off, v0, v1);
            }
        }
    };

    // Consumer: MMA over stage st, A-fragments pipelined 2 mi-tiles ahead
    auto compute = [&](int st) {
        const uint32_t uA  = sbase + st * STAGEB;
        const uint32_t uAl = uA + TILEB;
        const uint32_t uB  = uA + 2 * TILEB;
        const uint32_t uBl = uA + 3 * TILEB;
#pragma unroll
        for (int ks = 0; ks < 4; ks++) {
            uint32_t bh[4][2], bl[4][2];
            uint32_t ah[4][4], al[4][4];   // rotating A buffers (<=3 live)
            // 1) all B fragments
#pragma unroll
            for (int nj = 0; nj < 2; nj++) {
                const uint32_t off = (uint32_t)((wn * 32 + nj * 16 + bRow) * ROWB
                                                + (ks * 16 + bK) * 2);
                uint32_t rh[4], rl[4];
                ldsm_x4(uB + off, rh);
                ldsm_x4(uBl + off, rl);
                bh[nj * 2][0] = rh[0]; bh[nj * 2][1] = rh[1];
                bh[nj * 2 + 1][0] = rh[2]; bh[nj * 2 + 1][1] = rh[3];
                bl[nj * 2][0] = rl[0]; bl[nj * 2][1] = rl[1];
                bl[nj * 2 + 1][0] = rl[2]; bl[nj * 2 + 1][1] = rl[3];
            }
            // 2) A fragments for mi=0,1 up front
#pragma unroll
            for (int mi = 0; mi < 2; mi++) {
                const uint32_t off = (uint32_t)((wm * 64 + mi * 16 + aRow) * ROWB
                                                + (ks * 16 + aK) * 2);
                ldsm_x4(uA + off, ah[mi]);
                ldsm_x4(uAl + off, al[mi]);
            }
            // 3) mi loop: prefetch A(mi+2), then MMAs(mi)
#pragma unroll
            for (int mi = 0; mi < 4; mi++) {
                if (mi < 2) {
                    const int mj = mi + 2;
                    const uint32_t off = (uint32_t)((wm * 64 + mj * 16 + aRow) * ROWB
                                                    + (ks * 16 + aK) * 2);
                    ldsm_x4(uA + off, ah[mj]);
                    ldsm_x4(uAl + off, al[mj]);
                }
#pragma unroll
                for (int ni = 0; ni < 4; ni++) {
                    mma_bf16(acc[mi][ni], ah[mi], bh[ni]);
                    mma_bf16(acc[mi][ni], ah[mi], bl[ni]);
                    mma_bf16(acc[mi][ni], al[mi], bh[ni]);
                }
            }
        }
    };

    // Prologue: producers fill stage 0
    if (!consumer) produce(0, 0);
    __syncthreads();

    for (int c = 0; c < nchunk; c++) {
        if (consumer) {
            compute(c & 1);
        } else if (c + 1 < nchunk) {
            produce((c + 1) & 1, c + 1);   // runs under the MMA window
        }
        __syncthreads();
    }

    // Epilogue (consumers only)
    if (consumer) {
        const int g = lane >> 2, t = lane & 3;
#pragma unroll
        for (int mi = 0; mi < 4; mi++) {
#pragma unroll
            for (int half = 0; half < 2; half++) {
                const long r = (long)(rowA + wm * 64 + mi * 16 + g + half * 8);
#pragma unroll
                for (int ni = 0; ni < 4; ni++) {
                    const int col = rowB + wn * 32 + ni * 8 + t * 2;
                    *reinterpret_cast<float2*>(&C[r * ldC + col]) =
                        make_float2(acc[mi][ni][half * 2 + 0] * alpha,
                                    acc[mi][ni][half * 2 + 1] * alpha);
                }
            }
        }
    }
}

// ---------------------------------------------------------------------------
// Transpose: out[c,r] = in[r,c]; input ld = ldIn, output ld = R; batched via z
// ---------------------------------------------------------------------------
__global__ __launch_bounds__(256)
void transpose_kernel(const float* __restrict__ in, float* __restrict__ out,
                      int R, int ldIn, long sIn, long sOut)
{
    __shared__ float t[32][33];
    in  += (long)blockIdx.z * sIn;
    out += (long)blockIdx.z * sOut;
    const int rb = blockIdx.y * 32, cb = blockIdx.x * 32;
    const int x = threadIdx.x, y = threadIdx.y;  // 32 x 8
#pragma unroll
    for (int j = 0; j < 32; j += 8)
        t[y + j][x] = in[(long)(rb + y + j) * ldIn + cb + x];
    __syncthreads();
#pragma unroll
    for (int j = 0; j < 32; j += 8)
        out[(long)(cb + y + j) * R + rb + x] = t[x][y + j];
}

// ---------------------------------------------------------------------------
// Row softmax over SEQ=2048 columns, in-place fp32. One 256-thread CTA/row.
// ---------------------------------------------------------------------------
__global__ __launch_bounds__(256)
void softmax_kernel(float* __restrict__ S)
{
    float* p = S + (long)blockIdx.x * SEQ;
    const int tid  = threadIdx.x;
    const int lane = tid & 31;
    const int warp = tid >> 5;
    __shared__ float red[8];

    float4 u0 = *reinterpret_cast<const float4*>(&p[tid * 8]);
    float4 u1 = *reinterpret_cast<const float4*>(&p[tid * 8 + 4]);
    float v[8] = {u0.x, u0.y, u0.z, u0.w, u1.x, u1.y, u1.z, u1.w};

    float m = v[0];
#pragma unroll
    for (int i = 1; i < 8; i++) m = fmaxf(m, v[i]);
#pragma unroll
    for (int o = 16; o > 0; o >>= 1) m = fmaxf(m, __shfl_xor_sync(0xffffffffu, m, o));
    if (lane == 0) red[warp] = m;
    __syncthreads();
    m = red[0];
#pragma unroll
    for (int i = 1; i < 8; i++) m = fmaxf(m, red[i]);
    __syncthreads();

    float s = 0.0f;
#pragma unroll
    for (int i = 0; i < 8; i++) { v[i] = __expf(v[i] - m); s += v[i]; }
#pragma unroll
    for (int o = 16; o > 0; o >>= 1) s += __shfl_xor_sync(0xffffffffu, s, o);
    if (lane == 0) red[warp] = s;
    __syncthreads();
    s = red[0];
#pragma unroll
    for (int i = 1; i < 8; i++) s += red[i];

    float inv = __frcp_rn(s);
    float4 w0, w1;
    w0.x = v[0] * inv; w0.y = v[1] * inv; w0.z = v[2] * inv; w0.w = v[3] * inv;
    w1.x = v[4] * inv; w1.y = v[5] * inv; w1.z = v[6] * inv; w1.w = v[7] * inv;
    *reinterpret_cast<float4*>(&p[tid * 8])     = w0;
    *reinterpret_cast<float4*>(&p[tid * 8 + 4]) = w1;
}

// ---------------------------------------------------------------------------
extern "C" void kernel_launch(void* const* d_in, const int* in_sizes, int n_in,
                              void* d_out, int out_size)
{
    const float* x  = (const float*)d_in[0];
    const float* Wq = (const float*)d_in[1];
    const float* Wk = (const float*)d_in[2];
    const float* Wv = (const float*)d_in[3];
    float* out = (float*)d_out;

    float *QKV, *Vt, *S, *WT;
    cudaGetSymbolAddress((void**)&QKV, g_QKV);
    cudaGetSymbolAddress((void**)&Vt,  g_Vt);
    cudaGetSymbolAddress((void**)&S,   g_S);
    cudaGetSymbolAddress((void**)&WT,  g_WT);

    cudaFuncSetAttribute(tc_gemm10, cudaFuncAttributeMaxDynamicSharedMemorySize, SMEMB);

    const dim3 gemmBlk(512);   // tc_gemm10 only
    const dim3 blk256(256);    // softmax
    const dim3 tblk(32, 8);    // transpose
    const int M_proj = BATCH * SEQ;  // 16384

    // 1) Transpose weights into concat WT [1536, 512] (K-major rows)
    {
        dim3 g(DIM / 32, DIM / 32, 1);
        transpose_kernel<<<g, tblk>>>(Wq, WT + 0L * DIM * DIM, DIM, DIM, 0, 0);
        transpose_kernel<<<g, tblk>>>(Wk, WT + 1L * DIM * DIM, DIM, DIM, 0, 0);
        transpose_kernel<<<g, tblk>>>(Wv, WT + 2L * DIM * DIM, DIM, DIM, 0, 0);
    }

    // 2) Fused QKV projection: QKV[16384,1536] = x[16384,512] @ WT^T
    {
        dim3 g(NQKV / 128, M_proj / 128, 1);
        tc_gemm10<<<g, gemmBlk, SMEMB>>>(x, WT, QKV, M_proj, NQKV, DIM,
                                         DIM, DIM, NQKV, 0, 0, 0, 1.0f);
    }

    // 3) Transpose V (QKV cols 1024..1535) per batch -> Vt [512, 2048]
    {
        dim3 g(DIM / 32, SEQ / 32, BATCH);
        transpose_kernel<<<g, tblk>>>(QKV + 2 * DIM, Vt, SEQ, NQKV,
                                      (long)SEQ * NQKV, (long)DIM * SEQ);
    }

    // 4) Scores: S[b] = Q[b] @ K[b]^T / sqrt(D)
    {
        const float scale = 0.044194173824159216f;  // 1/sqrt(512)
        dim3 g(SEQ / 128, SEQ / 128, BATCH);
        tc_gemm10<<<g, gemmBlk, SMEMB>>>(QKV, QKV + DIM, S, SEQ, SEQ, DIM,
                                         NQKV, NQKV, SEQ,
                                         (long)SEQ * NQKV, (long)SEQ * NQKV,
                                         (long)SEQ * SEQ, scale);
    }

    // 5) Softmax rows (in place)
    softmax_kernel<<<BATCH * SEQ, blk256>>>(S);

    // 6) out[b] = P[b] @ Vt[b]^T
    {
        dim3 g(DIM / 128, SEQ / 128, BATCH);
        tc_gemm10<<<g, gemmBlk, SMEMB>>>(S, Vt, out, SEQ, DIM, SEQ,
                                         SEQ, SEQ, DIM,
                                         (long)SEQ * SEQ, (long)DIM * SEQ,
                                         (long)SEQ * DIM, 1.0f);
    }
}

// round 14
// speedup vs baseline: 1.3891x; 1.0423x over previous
#include <cuda_runtime.h>
#include <cuda_bf16.h>
#include <cstdint>

#define BATCH 8
#define SEQ   2048
#define DIM   512
#define NQKV  1536   // 3*DIM

// ---------------------------------------------------------------------------
// Scratch (device globals)
// ---------------------------------------------------------------------------
__device__ __align__(16) float g_QKV[(long)BATCH * SEQ * NQKV];  // 96 MB
__device__ __align__(16) float g_Vt [(long)BATCH * DIM * SEQ];   // 32 MB
__device__ __align__(16) float g_S  [(long)BATCH * SEQ * SEQ];   // 128 MB
__device__ __align__(16) float g_WT [(long)NQKV * DIM];          // 3 MB

// ---------------------------------------------------------------------------
// PTX helpers (baseline ISA: ldmatrix, mma.sync, mbarrier — sm_90 baseline)
// ---------------------------------------------------------------------------
__device__ __forceinline__ uint32_t smem_u32(const void* p) {
    uint32_t a;
    asm("{ .reg .u64 t; cvta.to.shared.u64 t, %1; cvt.u32.u64 %0, t; }"
        : "=r"(a) : "l"(p));
    return a;
}
__device__ __forceinline__ void ldsm_x4(uint32_t addr, uint32_t* r) {
    asm volatile("ldmatrix.sync.aligned.m8n8.x4.shared.b16 {%0,%1,%2,%3}, [%4];"
                 : "=r"(r[0]), "=r"(r[1]), "=r"(r[2]), "=r"(r[3]) : "r"(addr));
}
__device__ __forceinline__ void mma_bf16(float* c, const uint32_t* a, const uint32_t* b) {
    asm volatile(
        "mma.sync.aligned.m16n8k16.row.col.f32.bf16.bf16.f32 "
        "{%0,%1,%2,%3}, {%4,%5,%6,%7}, {%8,%9}, {%0,%1,%2,%3};"
        : "+f"(c[0]), "+f"(c[1]), "+f"(c[2]), "+f"(c[3])
        : "r"(a[0]), "r"(a[1]), "r"(a[2]), "r"(a[3]), "r"(b[0]), "r"(b[1]));
}

#define MBAR_INIT(mbar, cnt) \
    asm volatile("mbarrier.init.shared.b64 [%0], %1;" :: "r"(mbar), "r"((uint32_t)(cnt)) : "memory")
#define MBAR_ARRIVE(mbar) \
    asm volatile("mbarrier.arrive.shared.b64 _, [%0];" :: "r"(mbar) : "memory")
#define MBAR_WAIT(mbar_addr, parity) do {                                          \
    uint32_t _m = (mbar_addr); uint32_t _p = (parity); uint32_t _done;             \
    asm volatile("{ .reg .pred p; mbarrier.try_wait.parity.acquire.cta.shared::cta.b64 p, [%1], %2; " \
                 "selp.b32 %0, 1, 0, p; }" : "=r"(_done) : "r"(_m), "r"(_p) : "memory"); \
    if (!_done) {                                                                  \
        asm volatile("{ .reg .pred P1; WL_%=: mbarrier.try_wait.parity.acquire.cta.shared::cta.b64 P1, [%0], %1, 0x989680; " \
                     "@P1 bra.uni WD_%=; bra.uni WL_%=; WD_%=: }"                  \
                     :: "r"(_m), "r"(_p) : "memory");                              \
    }                                                                              \
} while (0)

// Convert 8 consecutive floats -> 16B hi + 16B lo bf16, store to smem
__device__ __forceinline__ void cvt_store16(char* hi, char* lo, uint32_t off,
                                            float4 v0, float4 v1) {
    __nv_bfloat162 h[4], l[4];
    h[0] = __floats2bfloat162_rn(v0.x, v0.y);
    h[1] = __floats2bfloat162_rn(v0.z, v0.w);
    h[2] = __floats2bfloat162_rn(v1.x, v1.y);
    h[3] = __floats2bfloat162_rn(v1.z, v1.w);
    l[0] = __floats2bfloat162_rn(v0.x - __bfloat162float(h[0].x),
                                 v0.y - __bfloat162float(h[0].y));
    l[1] = __floats2bfloat162_rn(v0.z - __bfloat162float(h[1].x),
                                 v0.w - __bfloat162float(h[1].y));
    l[2] = __floats2bfloat162_rn(v1.x - __bfloat162float(h[2].x),
                                 v1.y - __bfloat162float(h[2].y));
    l[3] = __floats2bfloat162_rn(v1.z - __bfloat162float(h[3].x),
                                 v1.w - __bfloat162float(h[3].y));
    *reinterpret_cast<uint4*>(hi + off) = *reinterpret_cast<uint4*>(h);
    *reinterpret_cast<uint4*>(lo + off) = *reinterpret_cast<uint4*>(l);
}

// ---------------------------------------------------------------------------
// Tensor-core GEMM, WARP-SPECIALIZED with MBARRIER stage handoff:
// C[M,N] = alpha * A[M,K] @ B[N,K]^T, in-kernel split precision
// (hi+lo bf16, 3 MMA terms). CTA tile 128x128, K-chunk 64, double-buffered
// smem. 512 threads: warps 0-7 consumers (2M x 4N of 64x32 tiles), warps
// 8-15 producers (LDG->split->STS). NO block barrier in the main loop:
// per-stage full/empty mbarrier pairs decouple consumer warps from each
// other so the tensor pipe never drains at chunk boundaries.
// ---------------------------------------------------------------------------
#define KC     64
#define ROWB   144                 // 64 bf16 = 128B + 16B pad: conflict-free ldsm
#define TILEB  (128 * ROWB)        // 18432
#define STAGEB (4 * TILEB)         // Ahi, Alo, Bhi, Blo = 73728
#define MBAR_OFF (2 * STAGEB)      // 4 mbarriers: full0, full1, empty0, empty1
#define SMEMB  (MBAR_OFF + 64)

__global__ __launch_bounds__(512, 1)
void tc_gemm11(const float* __restrict__ A, const float* __restrict__ B,
               float* __restrict__ C, int M, int N, int K,
               int ldA, int ldB, int ldC, long sA, long sB, long sC, float alpha)
{
    extern __shared__ __align__(16) char smem[];
    const uint32_t sbase = smem_u32(smem);

    const long zb = blockIdx.z;
    A += zb * sA;
    B += zb * sB;
    C += zb * sC;

    const int tid  = threadIdx.x;
    const int wid  = tid >> 5;
    const int lane = tid & 31;
    const bool consumer = (wid < 8);

    const int rowA = blockIdx.y * 128;
    const int rowB = blockIdx.x * 128;
    const int nchunk = K / KC;

    const uint32_t mb_full0  = sbase + MBAR_OFF;
    const uint32_t mb_empty0 = sbase + MBAR_OFF + 16;

    if (tid == 0) {
        MBAR_INIT(mb_full0,       256);  // full stage 0 (producer arrivals)
        MBAR_INIT(mb_full0 + 8,   256);  // full stage 1
        MBAR_INIT(mb_empty0,      256);  // empty stage 0 (consumer arrivals)
        MBAR_INIT(mb_empty0 + 8,  256);  // empty stage 1
    }
    __syncthreads();

    // ---- consumer state ----
    const int wm = wid & 1;    // 2 warps along M (64 rows each)
    const int wn = wid >> 1;   // 4 warps along N (32 cols each)  [wid<8]
    const int aRow = lane & 15;
    const int aK   = (lane >> 4) * 8;
    const int bRow = (lane & 7) + ((lane >> 4) & 1) * 8;
    const int bK   = ((lane >> 3) & 1) * 8;

    // ---- producer state ----
    const int ptid = tid - 256;        // 0..255 for producers
    const int prow = ptid >> 3;        // 0..31 (row, advance by 32 per i)
    const int pseg = ptid & 7;         // 8-float k-segment within 64

    if (!consumer) {
        // ================= PRODUCER LOOP =================
        for (int c = 0; c < nchunk; c++) {
            const int st = c & 1;
            const uint32_t par = ((c >> 1) & 1) ^ 1;  // first two waits pass
            MBAR_WAIT(mb_empty0 + st * 8, par);
            const int kb = c * KC;
            char* base = smem + st * STAGEB;
#pragma unroll
            for (int i = 0; i < 4; i++) {
                const int r = prow + i * 32;
                const uint32_t off = (uint32_t)(r * ROWB + pseg * 16);
                {
                    const float* p = &A[(long)(rowA + r) * ldA + kb + pseg * 8];
                    float4 v0 = *reinterpret_cast<const float4*>(p);
                    float4 v1 = *reinterpret_cast<const float4*>(p + 4);
                    cvt_store16(base + 0 * TILEB, base + 1 * TILEB, off, v0, v1);
                }
                {
                    const float* p = &B[(long)(rowB + r) * ldB + kb + pseg * 8];
                    float4 v0 = *reinterpret_cast<const float4*>(p);
                    float4 v1 = *reinterpret_cast<const float4*>(p + 4);
                    cvt_store16(base + 2 * TILEB, base + 3 * TILEB, off, v0, v1);
                }
            }
            MBAR_ARRIVE(mb_full0 + st * 8);
        }
        return;
    }

    // ================= CONSUMER LOOP =================
    float acc[4][4][4];
#pragma unroll
    for (int i = 0; i < 4; i++)
#pragma unroll
        for (int j = 0; j < 4; j++)
#pragma unroll
            for (int k = 0; k < 4; k++) acc[i][j][k] = 0.0f;

    for (int c = 0; c < nchunk; c++) {
        const int st = c & 1;
        MBAR_WAIT(mb_full0 + st * 8, (c >> 1) & 1);

        const uint32_t uA  = sbase + st * STAGEB;
        const uint32_t uAl = uA + TILEB;
        const uint32_t uB  = uA + 2 * TILEB;
        const uint32_t uBl = uA + 3 * TILEB;
#pragma unroll
        for (int ks = 0; ks < 4; ks++) {
            uint32_t bh[4][2], bl[4][2];
#pragma unroll
            for (int nj = 0; nj < 2; nj++) {
                const uint32_t off = (uint32_t)((wn * 32 + nj * 16 + bRow) * ROWB
                                                + (ks * 16 + bK) * 2);
                uint32_t rh[4], rl[4];
                ldsm_x4(uB + off, rh);
                ldsm_x4(uBl + off, rl);
                bh[nj * 2][0] = rh[0]; bh[nj * 2][1] = rh[1];
                bh[nj * 2 + 1][0] = rh[2]; bh[nj * 2 + 1][1] = rh[3];
                bl[nj * 2][0] = rl[0]; bl[nj * 2][1] = rl[1];
                bl[nj * 2 + 1][0] = rl[2]; bl[nj * 2 + 1][1] = rl[3];
            }
#pragma unroll
            for (int mi = 0; mi < 4; mi++) {
                uint32_t ah[4], al[4];
                const uint32_t off = (uint32_t)((wm * 64 + mi * 16 + aRow) * ROWB
                                                + (ks * 16 + aK) * 2);
                ldsm_x4(uA + off, ah);
                ldsm_x4(uAl + off, al);
#pragma unroll
                for (int ni = 0; ni < 4; ni++) {
                    mma_bf16(acc[mi][ni], ah, bh[ni]);
                    mma_bf16(acc[mi][ni], ah, bl[ni]);
                    mma_bf16(acc[mi][ni], al, bh[ni]);
                }
            }
        }
        MBAR_ARRIVE(mb_empty0 + st * 8);
    }

    // Epilogue (consumers only)
    {
        const int g = lane >> 2, t = lane & 3;
#pragma unroll
        for (int mi = 0; mi < 4; mi++) {
#pragma unroll
            for (int half = 0; half < 2; half++) {
                const long r = (long)(rowA + wm * 64 + mi * 16 + g + half * 8);
#pragma unroll
                for (int ni = 0; ni < 4; ni++) {
                    const int col = rowB + wn * 32 + ni * 8 + t * 2;
                    *reinterpret_cast<float2*>(&C[r * ldC + col]) =
                        make_float2(acc[mi][ni][half * 2 + 0] * alpha,
                                    acc[mi][ni][half * 2 + 1] * alpha);
                }
            }
        }
    }
}

// ---------------------------------------------------------------------------
// Transpose: out[c,r] = in[r,c]; input ld = ldIn, output ld = R; batched via z
// ---------------------------------------------------------------------------
__global__ __launch_bounds__(256)
void transpose_kernel(const float* __restrict__ in, float* __restrict__ out,
                      int R, int ldIn, long sIn, long sOut)
{
    __shared__ float t[32][33];
    in  += (long)blockIdx.z * sIn;
    out += (long)blockIdx.z * sOut;
    const int rb = blockIdx.y * 32, cb = blockIdx.x * 32;
    const int x = threadIdx.x, y = threadIdx.y;  // 32 x 8
#pragma unroll
    for (int j = 0; j < 32; j += 8)
        t[y + j][x] = in[(long)(rb + y + j) * ldIn + cb + x];
    __syncthreads();
#pragma unroll
    for (int j = 0; j < 32; j += 8)
        out[(long)(cb + y + j) * R + rb + x] = t[x][y + j];
}

// ---------------------------------------------------------------------------
// Row softmax over SEQ=2048 columns, in-place fp32. One 256-thread CTA/row.
// ---------------------------------------------------------------------------
__global__ __launch_bounds__(256)
void softmax_kernel(float* __restrict__ S)
{
    float* p = S + (long)blockIdx.x * SEQ;
    const int tid  = threadIdx.x;
    const int lane = tid & 31;
    const int warp = tid >> 5;
    __shared__ float red[8];

    float4 u0 = *reinterpret_cast<const float4*>(&p[tid * 8]);
    float4 u1 = *reinterpret_cast<const float4*>(&p[tid * 8 + 4]);
    float v[8] = {u0.x, u0.y, u0.z, u0.w, u1.x, u1.y, u1.z, u1.w};

    float m = v[0];
#pragma unroll
    for (int i = 1; i < 8; i++) m = fmaxf(m, v[i]);
#pragma unroll
    for (int o = 16; o > 0; o >>= 1) m = fmaxf(m, __shfl_xor_sync(0xffffffffu, m, o));
    if (lane == 0) red[warp] = m;
    __syncthreads();
    m = red[0];
#pragma unroll
    for (int i = 1; i < 8; i++) m = fmaxf(m, red[i]);
    __syncthreads();

    float s = 0.0f;
#pragma unroll
    for (int i = 0; i < 8; i++) { v[i] = __expf(v[i] - m); s += v[i]; }
#pragma unroll
    for (int o = 16; o > 0; o >>= 1) s += __shfl_xor_sync(0xffffffffu, s, o);
    if (lane == 0) red[warp] = s;
    __syncthreads();
    s = red[0];
#pragma unroll
    for (int i = 1; i < 8; i++) s += red[i];

    float inv = __frcp_rn(s);
    float4 w0, w1;
    w0.x = v[0] * inv; w0.y = v[1] * inv; w0.z = v[2] * inv; w0.w = v[3] * inv;
    w1.x = v[4] * inv; w1.y = v[5] * inv; w1.z = v[6] * inv; w1.w = v[7] * inv;
    *reinterpret_cast<float4*>(&p[tid * 8])     = w0;
    *reinterpret_cast<float4*>(&p[tid * 8 + 4]) = w1;
}

// ---------------------------------------------------------------------------
extern "C" void kernel_launch(void* const* d_in, const int* in_sizes, int n_in,
                              void* d_out, int out_size)
{
    const float* x  = (const float*)d_in[0];
    const float* Wq = (const float*)d_in[1];
    const float* Wk = (const float*)d_in[2];
    const float* Wv = (const float*)d_in[3];
    float* out = (float*)d_out;

    float *QKV, *Vt, *S, *WT;
    cudaGetSymbolAddress((void**)&QKV, g_QKV);
    cudaGetSymbolAddress((void**)&Vt,  g_Vt);
    cudaGetSymbolAddress((void**)&S,   g_S);
    cudaGetSymbolAddress((void**)&WT,  g_WT);

    cudaFuncSetAttribute(tc_gemm11, cudaFuncAttributeMaxDynamicSharedMemorySize, SMEMB);

    const dim3 gemmBlk(512);   // tc_gemm11 only
    const dim3 blk256(256);    // softmax
    const dim3 tblk(32, 8);    // transpose
    const int M_proj = BATCH * SEQ;  // 16384

    // 1) Transpose weights into concat WT [1536, 512] (K-major rows)
    {
        dim3 g(DIM / 32, DIM / 32, 1);
        transpose_kernel<<<g, tblk>>>(Wq, WT + 0L * DIM * DIM, DIM, DIM, 0, 0);
        transpose_kernel<<<g, tblk>>>(Wk, WT + 1L * DIM * DIM, DIM, DIM, 0, 0);
        transpose_kernel<<<g, tblk>>>(Wv, WT + 2L * DIM * DIM, DIM, DIM, 0, 0);
    }

    // 2) Fused QKV projection: QKV[16384,1536] = x[16384,512] @ WT^T
    {
        dim3 g(NQKV / 128, M_proj / 128, 1);
        tc_gemm11<<<g, gemmBlk, SMEMB>>>(x, WT, QKV, M_proj, NQKV, DIM,
                                         DIM, DIM, NQKV, 0, 0, 0, 1.0f);
    }

    // 3) Transpose V (QKV cols 1024..1535) per batch -> Vt [512, 2048]
    {
        dim3 g(DIM / 32, SEQ / 32, BATCH);
        transpose_kernel<<<g, tblk>>>(QKV + 2 * DIM, Vt, SEQ, NQKV,
                                      (long)SEQ * NQKV, (long)DIM * SEQ);
    }

    // 4) Scores: S[b] = Q[b] @ K[b]^T / sqrt(D)
    {
        const float scale = 0.044194173824159216f;  // 1/sqrt(512)
        dim3 g(SEQ / 128, SEQ / 128, BATCH);
        tc_gemm11<<<g, gemmBlk, SMEMB>>>(QKV, QKV + DIM, S, SEQ, SEQ, DIM,
                                         NQKV, NQKV, SEQ,
                                         (long)SEQ * NQKV, (long)SEQ * NQKV,
                                         (long)SEQ * SEQ, scale);
    }

    // 5) Softmax rows (in place)
    softmax_kernel<<<BATCH * SEQ, blk256>>>(S);

    // 6) out[b] = P[b] @ Vt[b]^T
    {
        dim3 g(DIM / 128, SEQ / 128, BATCH);
        tc_gemm11<<<g, gemmBlk, SMEMB>>>(S, Vt, out, SEQ, DIM, SEQ,
                                         SEQ, SEQ, DIM,
                                         (long)SEQ * SEQ, (long)DIM * SEQ,
                                         (long)SEQ * DIM, 1.0f);
    }
}

// round 15
// speedup vs baseline: 1.7234x; 1.2406x over previous
#include <cuda_runtime.h>
#include <cuda_fp16.h>
#include <cstdint>

#define BATCH 8
#define SEQ   2048
#define DIM   512
#define NQKV  1536   // 3*DIM

// ---------------------------------------------------------------------------
// Scratch (device globals)
// ---------------------------------------------------------------------------
__device__ __align__(16) float g_QKV[(long)BATCH * SEQ * NQKV];  // 96 MB
__device__ __align__(16) float g_Vt [(long)BATCH * DIM * SEQ];   // 32 MB
__device__ __align__(16) float g_S  [(long)BATCH * SEQ * SEQ];   // 128 MB
__device__ __align__(16) float g_WT [(long)NQKV * DIM];          // 3 MB

// ---------------------------------------------------------------------------
// PTX helpers (baseline ISA: ldmatrix, mma.sync, mbarrier)
// ---------------------------------------------------------------------------
__device__ __forceinline__ uint32_t smem_u32(const void* p) {
    uint32_t a;
    asm("{ .reg .u64 t; cvta.to.shared.u64 t, %1; cvt.u32.u64 %0, t; }"
        : "=r"(a) : "l"(p));
    return a;
}
__device__ __forceinline__ void ldsm_x4(uint32_t addr, uint32_t* r) {
    asm volatile("ldmatrix.sync.aligned.m8n8.x4.shared.b16 {%0,%1,%2,%3}, [%4];"
                 : "=r"(r[0]), "=r"(r[1]), "=r"(r[2]), "=r"(r[3]) : "r"(addr));
}
__device__ __forceinline__ void mma_f16(float* c, const uint32_t* a, const uint32_t* b) {
    asm volatile(
        "mma.sync.aligned.m16n8k16.row.col.f32.f16.f16.f32 "
        "{%0,%1,%2,%3}, {%4,%5,%6,%7}, {%8,%9}, {%0,%1,%2,%3};"
        : "+f"(c[0]), "+f"(c[1]), "+f"(c[2]), "+f"(c[3])
        : "r"(a[0]), "r"(a[1]), "r"(a[2]), "r"(a[3]), "r"(b[0]), "r"(b[1]));
}

#define MBAR_INIT(mbar, cnt) \
    asm volatile("mbarrier.init.shared.b64 [%0], %1;" :: "r"(mbar), "r"((uint32_t)(cnt)) : "memory")
#define MBAR_ARRIVE(mbar) \
    asm volatile("mbarrier.arrive.shared.b64 _, [%0];" :: "r"(mbar) : "memory")
#define MBAR_WAIT(mbar_addr, parity) do {                                          \
    uint32_t _m = (mbar_addr); uint32_t _p = (parity); uint32_t _done;             \
    asm volatile("{ .reg .pred p; mbarrier.try_wait.parity.acquire.cta.shared::cta.b64 p, [%1], %2; " \
                 "selp.b32 %0, 1, 0, p; }" : "=r"(_done) : "r"(_m), "r"(_p) : "memory"); \
    if (!_done) {                                                                  \
        asm volatile("{ .reg .pred P1; WL_%=: mbarrier.try_wait.parity.acquire.cta.shared::cta.b64 P1, [%0], %1, 0x989680; " \
                     "@P1 bra.uni WD_%=; bra.uni WL_%=; WD_%=: }"                  \
                     :: "r"(_m), "r"(_p) : "memory");                              \
    }                                                                              \
} while (0)

// 8 floats -> fp16 hi (16B) + fp16 lo (16B)
__device__ __forceinline__ void cvt_split16(char* hi, char* lo, uint32_t off,
                                            float4 v0, float4 v1) {
    __half2 h[4], l[4];
    h[0] = __floats2half2_rn(v0.x, v0.y);
    h[1] = __floats2half2_rn(v0.z, v0.w);
    h[2] = __floats2half2_rn(v1.x, v1.y);
    h[3] = __floats2half2_rn(v1.z, v1.w);
    l[0] = __floats2half2_rn(v0.x - __low2float(h[0]), v0.y - __high2float(h[0]));
    l[1] = __floats2half2_rn(v0.z - __low2float(h[1]), v0.w - __high2float(h[1]));
    l[2] = __floats2half2_rn(v1.x - __low2float(h[2]), v1.y - __high2float(h[2]));
    l[3] = __floats2half2_rn(v1.z - __low2float(h[3]), v1.w - __high2float(h[3]));
    *reinterpret_cast<uint4*>(hi + off) = *reinterpret_cast<uint4*>(h);
    *reinterpret_cast<uint4*>(lo + off) = *reinterpret_cast<uint4*>(l);
}
// 8 floats -> fp16 hi only (16B)
__device__ __forceinline__ void cvt_hi16(char* hi, uint32_t off, float4 v0, float4 v1) {
    __half2 h[4];
    h[0] = __floats2half2_rn(v0.x, v0.y);
    h[1] = __floats2half2_rn(v0.z, v0.w);
    h[2] = __floats2half2_rn(v1.x, v1.y);
    h[3] = __floats2half2_rn(v1.z, v1.w);
    *reinterpret_cast<uint4*>(hi + off) = *reinterpret_cast<uint4*>(h);
}

// ---------------------------------------------------------------------------
// Tensor-core GEMM, WARP-SPECIALIZED, mbarrier handoff, FP16 2-TERM SPLIT-A:
// C[M,N] = alpha * A[M,K] @ B[N,K]^T ; A = Ah + Al (fp16), B ~= Bh (fp16).
// acc += Ah*Bh + Al*Bh (fp32 accumulate). CTA tile 128x128, K-chunk 64,
// double-buffered. 512 threads: warps 0-7 consumers (2M x 4N of 64x32),
// warps 8-15 producers.
// ---------------------------------------------------------------------------
#define KC     64
#define ROWB   144                 // 64 fp16 = 128B + 16B pad: conflict-free ldsm
#define TILEB  (128 * ROWB)        // 18432
#define STAGEB (3 * TILEB)         // Ah, Al, Bh = 55296
#define MBAR_OFF (2 * STAGEB)      // 110592
#define SMEMB  (MBAR_OFF + 64)

__global__ __launch_bounds__(512, 1)
void tc_gemm12(const float* __restrict__ A, const float* __restrict__ B,
               float* __restrict__ C, int M, int N, int K,
               int ldA, int ldB, int ldC, long sA, long sB, long sC, float alpha)
{
    extern __shared__ __align__(16) char smem[];
    const uint32_t sbase = smem_u32(smem);

    const long zb = blockIdx.z;
    A += zb * sA;
    B += zb * sB;
    C += zb * sC;

    const int tid  = threadIdx.x;
    const int wid  = tid >> 5;
    const int lane = tid & 31;
    const bool consumer = (wid < 8);

    const int rowA = blockIdx.y * 128;
    const int rowB = blockIdx.x * 128;
    const int nchunk = K / KC;

    const uint32_t mb_full0  = sbase + MBAR_OFF;
    const uint32_t mb_empty0 = sbase + MBAR_OFF + 16;

    if (tid == 0) {
        MBAR_INIT(mb_full0,       256);
        MBAR_INIT(mb_full0 + 8,   256);
        MBAR_INIT(mb_empty0,      256);
        MBAR_INIT(mb_empty0 + 8,  256);
    }
    __syncthreads();

    // ---- consumer state ----
    const int wm = wid & 1;    // 2 warps along M (64 rows each)
    const int wn = wid >> 1;   // 4 warps along N (32 cols each)
    const int aRow = lane & 15;
    const int aK   = (lane >> 4) * 8;
    const int bRow = (lane & 7) + ((lane >> 4) & 1) * 8;
    const int bK   = ((lane >> 3) & 1) * 8;

    // ---- producer state ----
    const int ptid = tid - 256;
    const int prow = ptid >> 3;        // 0..31
    const int pseg = ptid & 7;         // 8-float k-segment within 64

    if (!consumer) {
        // ================= PRODUCER LOOP =================
        for (int c = 0; c < nchunk; c++) {
            const int st = c & 1;
            const uint32_t par = ((c >> 1) & 1) ^ 1;  // first two waits pass
            MBAR_WAIT(mb_empty0 + st * 8, par);
            const int kb = c * KC;
            char* base = smem + st * STAGEB;
#pragma unroll
            for (int i = 0; i < 4; i++) {
                const int r = prow + i * 32;
                const uint32_t off = (uint32_t)(r * ROWB + pseg * 16);
                {
                    const float* p = &A[(long)(rowA + r) * ldA + kb + pseg * 8];
                    float4 v0 = *reinterpret_cast<const float4*>(p);
                    float4 v1 = *reinterpret_cast<const float4*>(p + 4);
                    cvt_split16(base + 0 * TILEB, base + 1 * TILEB, off, v0, v1);
                }
                {
                    const float* p = &B[(long)(rowB + r) * ldB + kb + pseg * 8];
                    float4 v0 = *reinterpret_cast<const float4*>(p);
                    float4 v1 = *reinterpret_cast<const float4*>(p + 4);
                    cvt_hi16(base + 2 * TILEB, off, v0, v1);
                }
            }
            MBAR_ARRIVE(mb_full0 + st * 8);
        }
        return;
    }

    // ================= CONSUMER LOOP =================
    float acc[4][4][4];
#pragma unroll
    for (int i = 0; i < 4; i++)
#pragma unroll
        for (int j = 0; j < 4; j++)
#pragma unroll
            for (int k = 0; k < 4; k++) acc[i][j][k] = 0.0f;

    for (int c = 0; c < nchunk; c++) {
        const int st = c & 1;
        MBAR_WAIT(mb_full0 + st * 8, (c >> 1) & 1);

        const uint32_t uAh = sbase + st * STAGEB;
        const uint32_t uAl = uAh + TILEB;
        const uint32_t uBh = uAh + 2 * TILEB;
#pragma unroll
        for (int ks = 0; ks < 4; ks++) {
            uint32_t bh[4][2];
#pragma unroll
            for (int nj = 0; nj < 2; nj++) {
                const uint32_t off = (uint32_t)((wn * 32 + nj * 16 + bRow) * ROWB
                                                + (ks * 16 + bK) * 2);
                uint32_t rh[4];
                ldsm_x4(uBh + off, rh);
                bh[nj * 2][0] = rh[0]; bh[nj * 2][1] = rh[1];
                bh[nj * 2 + 1][0] = rh[2]; bh[nj * 2 + 1][1] = rh[3];
            }
#pragma unroll
            for (int mi = 0; mi < 4; mi++) {
                uint32_t ah[4], al[4];
                const uint32_t off = (uint32_t)((wm * 64 + mi * 16 + aRow) * ROWB
                                                + (ks * 16 + aK) * 2);
                ldsm_x4(uAh + off, ah);
                ldsm_x4(uAl + off, al);
#pragma unroll
                for (int ni = 0; ni < 4; ni++) {
                    mma_f16(acc[mi][ni], ah, bh[ni]);
                    mma_f16(acc[mi][ni], al, bh[ni]);
                }
            }
        }
        MBAR_ARRIVE(mb_empty0 + st * 8);
    }

    // Epilogue (consumers only)
    {
        const int g = lane >> 2, t = lane & 3;
#pragma unroll
        for (int mi = 0; mi < 4; mi++) {
#pragma unroll
            for (int half = 0; half < 2; half++) {
                const long r = (long)(rowA + wm * 64 + mi * 16 + g + half * 8);
#pragma unroll
                for (int ni = 0; ni < 4; ni++) {
                    const int col = rowB + wn * 32 + ni * 8 + t * 2;
                    *reinterpret_cast<float2*>(&C[r * ldC + col]) =
                        make_float2(acc[mi][ni][half * 2 + 0] * alpha,
                                    acc[mi][ni][half * 2 + 1] * alpha);
                }
            }
        }
    }
}

// ---------------------------------------------------------------------------
// Transpose: out[c,r] = in[r,c]; input ld = ldIn, output ld = R; batched via z
// ---------------------------------------------------------------------------
__global__ __launch_bounds__(256)
void transpose_kernel(const float* __restrict__ in, float* __restrict__ out,
                      int R, int ldIn, long sIn, long sOut)
{
    __shared__ float t[32][33];
    in  += (long)blockIdx.z * sIn;
    out += (long)blockIdx.z * sOut;
    const int rb = blockIdx.y * 32, cb = blockIdx.x * 32;
    const int x = threadIdx.x, y = threadIdx.y;  // 32 x 8
#pragma unroll
    for (int j = 0; j < 32; j += 8)
        t[y + j][x] = in[(long)(rb + y + j) * ldIn + cb + x];
    __syncthreads();
#pragma unroll
    for (int j = 0; j < 32; j += 8)
        out[(long)(cb + y + j) * R + rb + x] = t[x][y + j];
}

// ---------------------------------------------------------------------------
// Row softmax over SEQ=2048 columns, in-place fp32. One 256-thread CTA/row.
// ---------------------------------------------------------------------------
__global__ __launch_bounds__(256)
void softmax_kernel(float* __restrict__ S)
{
    float* p = S + (long)blockIdx.x * SEQ;
    const int tid  = threadIdx.x;
    const int lane = tid & 31;
    const int warp = tid >> 5;
    __shared__ float red[8];

    float4 u0 = *reinterpret_cast<const float4*>(&p[tid * 8]);
    float4 u1 = *reinterpret_cast<const float4*>(&p[tid * 8 + 4]);
    float v[8] = {u0.x, u0.y, u0.z, u0.w, u1.x, u1.y, u1.z, u1.w};

    float m = v[0];
#pragma unroll
    for (int i = 1; i < 8; i++) m = fmaxf(m, v[i]);
#pragma unroll
    for (int o = 16; o > 0; o >>= 1) m = fmaxf(m, __shfl_xor_sync(0xffffffffu, m, o));
    if (lane == 0) red[warp] = m;
    __syncthreads();
    m = red[0];
#pragma unroll
    for (int i = 1; i < 8; i++) m = fmaxf(m, red[i]);
    __syncthreads();

    float s = 0.0f;
#pragma unroll
    for (int i = 0; i < 8; i++) { v[i] = __expf(v[i] - m); s += v[i]; }
#pragma unroll
    for (int o = 16; o > 0; o >>= 1) s += __shfl_xor_sync(0xffffffffu, s, o);
    if (lane == 0) red[warp] = s;
    __syncthreads();
    s = red[0];
#pragma unroll
    for (int i = 1; i < 8; i++) s += red[i];

    float inv = __frcp_rn(s);
    float4 w0, w1;
    w0.x = v[0] * inv; w0.y = v[1] * inv; w0.z = v[2] * inv; w0.w = v[3] * inv;
    w1.x = v[4] * inv; w1.y = v[5] * inv; w1.z = v[6] * inv; w1.w = v[7] * inv;
    *reinterpret_cast<float4*>(&p[tid * 8])     = w0;
    *reinterpret_cast<float4*>(&p[tid * 8 + 4]) = w1;
}

// ---------------------------------------------------------------------------
extern "C" void kernel_launch(void* const* d_in, const int* in_sizes, int n_in,
                              void* d_out, int out_size)
{
    const float* x  = (const float*)d_in[0];
    const float* Wq = (const float*)d_in[1];
    const float* Wk = (const float*)d_in[2];
    const float* Wv = (const float*)d_in[3];
    float* out = (float*)d_out;

    float *QKV, *Vt, *S, *WT;
    cudaGetSymbolAddress((void**)&QKV, g_QKV);
    cudaGetSymbolAddress((void**)&Vt,  g_Vt);
    cudaGetSymbolAddress((void**)&S,   g_S);
    cudaGetSymbolAddress((void**)&WT,  g_WT);

    cudaFuncSetAttribute(tc_gemm12, cudaFuncAttributeMaxDynamicSharedMemorySize, SMEMB);

    const dim3 gemmBlk(512);   // tc_gemm12 only
    const dim3 blk256(256);    // softmax
    const dim3 tblk(32, 8);    // transpose
    const int M_proj = BATCH * SEQ;  // 16384

    // 1) Transpose weights into concat WT [1536, 512] (K-major rows)
    {
        dim3 g(DIM / 32, DIM / 32, 1);
        transpose_kernel<<<g, tblk>>>(Wq, WT + 0L * DIM * DIM, DIM, DIM, 0, 0);
        transpose_kernel<<<g, tblk>>>(Wk, WT + 1L * DIM * DIM, DIM, DIM, 0, 0);
        transpose_kernel<<<g, tblk>>>(Wv, WT + 2L * DIM * DIM, DIM, DIM, 0, 0);
    }

    // 2) Fused QKV projection: QKV[16384,1536] = x[16384,512] @ WT^T
    //    (x is split-A side: full hi/lo precision; W rounded to fp16)
    {
        dim3 g(NQKV / 128, M_proj / 128, 1);
        tc_gemm12<<<g, gemmBlk, SMEMB>>>(x, WT, QKV, M_proj, NQKV, DIM,
                                         DIM, DIM, NQKV, 0, 0, 0, 1.0f);
    }

    // 3) Transpose V (QKV cols 1024..1535) per batch -> Vt [512, 2048]
    {
        dim3 g(DIM / 32, SEQ / 32, BATCH);
        transpose_kernel<<<g, tblk>>>(QKV + 2 * DIM, Vt, SEQ, NQKV,
                                      (long)SEQ * NQKV, (long)DIM * SEQ);
    }

    // 4) Scores: S[b] = Q[b] @ K[b]^T / sqrt(D)
    {
        const float scale = 0.044194173824159216f;  // 1/sqrt(512)
        dim3 g(SEQ / 128, SEQ / 128, BATCH);
        tc_gemm12<<<g, gemmBlk, SMEMB>>>(QKV, QKV + DIM, S, SEQ, SEQ, DIM,
                                         NQKV, NQKV, SEQ,
                                         (long)SEQ * NQKV, (long)SEQ * NQKV,
                                         (long)SEQ * SEQ, scale);
    }

    // 5) Softmax rows (in place)
    softmax_kernel<<<BATCH * SEQ, blk256>>>(S);

    // 6) out[b] = P[b] @ Vt[b]^T  (P split hi/lo; V rounded to fp16)
    {
        dim3 g(DIM / 128, SEQ / 128, BATCH);
        tc_gemm12<<<g, gemmBlk, SMEMB>>>(S, Vt, out, SEQ, DIM, SEQ,
                                         SEQ, SEQ, DIM,
                                         (long)SEQ * SEQ, (long)DIM * SEQ,
                                         (long)SEQ * DIM, 1.0f);
    }
}

// round 16
// speedup vs baseline: 1.8444x; 1.0702x over previous
#include <cuda_runtime.h>
#include <cuda_fp16.h>
#include <cstdint>

#define BATCH 8
#define SEQ   2048
#define DIM   512
#define NQKV  1536   // 3*DIM

// ---------------------------------------------------------------------------
// Scratch (device globals) — fp16 pre-split operands
// ---------------------------------------------------------------------------
__device__ __align__(16) __half g_xh  [(long)BATCH * SEQ * DIM];   // 16 MB
__device__ __align__(16) __half g_xl  [(long)BATCH * SEQ * DIM];   // 16 MB
__device__ __align__(16) __half g_WTh [(long)NQKV * DIM];          // 1.5 MB
__device__ __align__(16) __half g_QKVh[(long)BATCH * SEQ * NQKV];  // 48 MB
__device__ __align__(16) __half g_QKVl[(long)BATCH * SEQ * NQKV];  // 48 MB
__device__ __align__(16) __half g_Vth [(long)BATCH * DIM * SEQ];   // 16 MB
__device__ __align__(16) __half g_Ph  [(long)BATCH * SEQ * SEQ];   // 64 MB
__device__ __align__(16) __half g_Pl  [(long)BATCH * SEQ * SEQ];   // 64 MB
__device__ __align__(16) float  g_S   [(long)BATCH * SEQ * SEQ];   // 128 MB

// ---------------------------------------------------------------------------
// PTX helpers (baseline ISA: ldmatrix, mma.sync, cp.async, mbarrier)
// ---------------------------------------------------------------------------
__device__ __forceinline__ uint32_t smem_u32(const void* p) {
    uint32_t a;
    asm("{ .reg .u64 t; cvta.to.shared.u64 t, %1; cvt.u32.u64 %0, t; }"
        : "=r"(a) : "l"(p));
    return a;
}
__device__ __forceinline__ void ldsm_x4(uint32_t addr, uint32_t* r) {
    asm volatile("ldmatrix.sync.aligned.m8n8.x4.shared.b16 {%0,%1,%2,%3}, [%4];"
                 : "=r"(r[0]), "=r"(r[1]), "=r"(r[2]), "=r"(r[3]) : "r"(addr));
}
__device__ __forceinline__ void mma_f16(float* c, const uint32_t* a, const uint32_t* b) {
    asm volatile(
        "mma.sync.aligned.m16n8k16.row.col.f32.f16.f16.f32 "
        "{%0,%1,%2,%3}, {%4,%5,%6,%7}, {%8,%9}, {%0,%1,%2,%3};"
        : "+f"(c[0]), "+f"(c[1]), "+f"(c[2]), "+f"(c[3])
        : "r"(a[0]), "r"(a[1]), "r"(a[2]), "r"(a[3]), "r"(b[0]), "r"(b[1]));
}
__device__ __forceinline__ void cp16(uint32_t dst, const void* src) {
    asm volatile("cp.async.cg.shared.global [%0], [%1], 16;" :: "r"(dst), "l"(src));
}
#define CP_COMMIT() asm volatile("cp.async.commit_group;" ::: "memory")
#define CP_WAIT0()  asm volatile("cp.async.wait_group 0;" ::: "memory")

#define MBAR_INIT(mbar, cnt) \
    asm volatile("mbarrier.init.shared.b64 [%0], %1;" :: "r"(mbar), "r"((uint32_t)(cnt)) : "memory")
#define MBAR_ARRIVE(mbar) \
    asm volatile("mbarrier.arrive.shared.b64 _, [%0];" :: "r"(mbar) : "memory")
#define MBAR_WAIT(mbar_addr, parity) do {                                          \
    uint32_t _m = (mbar_addr); uint32_t _p = (parity); uint32_t _done;             \
    asm volatile("{ .reg .pred p; mbarrier.try_wait.parity.acquire.cta.shared::cta.b64 p, [%1], %2; " \
                 "selp.b32 %0, 1, 0, p; }" : "=r"(_done) : "r"(_m), "r"(_p) : "memory"); \
    if (!_done) {                                                                  \
        asm volatile("{ .reg .pred P1; WL_%=: mbarrier.try_wait.parity.acquire.cta.shared::cta.b64 P1, [%0], %1, 0x989680; " \
                     "@P1 bra.uni WD_%=; bra.uni WL_%=; WD_%=: }"                  \
                     :: "r"(_m), "r"(_p) : "memory");                              \
    }                                                                              \
} while (0)

__device__ __forceinline__ void split_h(float v, __half& h, __half& l) {
    h = __float2half_rn(v);
    l = __float2half_rn(v - __half2float(h));
}

// ---------------------------------------------------------------------------
// Tensor-core GEMM, WARP-SPECIALIZED, mbarrier handoff, FP16 2-TERM SPLIT-A,
// PRE-SPLIT GMEM operands (Ah, Al, Bh all fp16 K-major):
// C[M,N] = alpha * (Ah+Al)[M,K] @ Bh[N,K]^T, fp32 accumulate.
// CTA tile 128x128, K-chunk 64, double-buffered. 512 threads: warps 0-7
// consumers (4M x 2N grid of 32x64 tiles — minimal ldsm traffic), warps
// 8-15 producers (pure cp.async 16B copies, no conversion).
// EPI 0: fp32 out; EPI 1: fp16 hi/lo pair out.
// ---------------------------------------------------------------------------
#define KC     64
#define ROWB   144                 // 64 fp16 = 128B + 16B pad: conflict-free ldsm
#define TILEB  (128 * ROWB)        // 18432
#define STAGEB (3 * TILEB)         // Ah, Al, Bh = 55296
#define MBAR_OFF (2 * STAGEB)      // 110592
#define SMEMB  (MBAR_OFF + 64)

template <int EPI>
__global__ __launch_bounds__(512, 1)
void tc_gemm13(const __half* __restrict__ Ah, const __half* __restrict__ Al,
               const __half* __restrict__ Bh,
               float* __restrict__ Cf,
               __half* __restrict__ Chi, __half* __restrict__ Clo,
               int M, int N, int K, int ldA, int ldB, int ldC,
               long sA, long sB, long sC, float alpha)
{
    extern __shared__ __align__(16) char smem[];
    const uint32_t sbase = smem_u32(smem);

    const long zb = blockIdx.z;
    Ah += zb * sA; Al += zb * sA;
    Bh += zb * sB;

    const int tid  = threadIdx.x;
    const int wid  = tid >> 5;
    const int lane = tid & 31;
    const bool consumer = (wid < 8);

    const int rowA = blockIdx.y * 128;
    const int rowB = blockIdx.x * 128;
    const int nchunk = K / KC;

    const uint32_t mb_full0  = sbase + MBAR_OFF;
    const uint32_t mb_empty0 = sbase + MBAR_OFF + 16;

    if (tid == 0) {
        MBAR_INIT(mb_full0,       256);
        MBAR_INIT(mb_full0 + 8,   256);
        MBAR_INIT(mb_empty0,      256);
        MBAR_INIT(mb_empty0 + 8,  256);
    }
    __syncthreads();

    // ---- producer state: 1024 16B-chunks per tile; 4 per thread per tile ----
    const int ptid = tid - 256;

    if (!consumer) {
        for (int c = 0; c < nchunk; c++) {
            const int st = c & 1;
            const uint32_t par = ((c >> 1) & 1) ^ 1;  // first two waits pass
            MBAR_WAIT(mb_empty0 + st * 8, par);
            const int kb = c * KC;
            const uint32_t base = sbase + st * STAGEB;
#pragma unroll
            for (int i = 0; i < 4; i++) {
                const int cid = ptid + i * 256;        // 0..1023
                const int r   = cid >> 3;              // row 0..127
                const int sg  = cid & 7;               // 16B segment
                const uint32_t off = (uint32_t)(r * ROWB + sg * 16);
                cp16(base + 0 * TILEB + off, Ah + (long)(rowA + r) * ldA + kb + sg * 8);
                cp16(base + 1 * TILEB + off, Al + (long)(rowA + r) * ldA + kb + sg * 8);
                cp16(base + 2 * TILEB + off, Bh + (long)(rowB + r) * ldB + kb + sg * 8);
            }
            CP_COMMIT();
            CP_WAIT0();
            MBAR_ARRIVE(mb_full0 + st * 8);
        }
        return;
    }

    // ---- consumer state: 4M x 2N grid of 32x64 warp tiles ----
    const int wm = wid & 3;    // 4 warps along M (32 rows each)
    const int wn = wid >> 2;   // 2 warps along N (64 cols each)
    const int aRow = lane & 15;
    const int aK   = (lane >> 4) * 8;
    const int bRow = (lane & 7) + ((lane >> 4) & 1) * 8;
    const int bK   = ((lane >> 3) & 1) * 8;

    float acc[2][8][4];
#pragma unroll
    for (int i = 0; i < 2; i++)
#pragma unroll
        for (int j = 0; j < 8; j++)
#pragma unroll
            for (int k = 0; k < 4; k++) acc[i][j][k] = 0.0f;

    for (int c = 0; c < nchunk; c++) {
        const int st = c & 1;
        MBAR_WAIT(mb_full0 + st * 8, (c >> 1) & 1);

        const uint32_t uAh = sbase + st * STAGEB;
        const uint32_t uAl = uAh + TILEB;
        const uint32_t uBh = uAh + 2 * TILEB;
#pragma unroll
        for (int ks = 0; ks < 4; ks++) {
            uint32_t bh[8][2];
#pragma unroll
            for (int nj = 0; nj < 4; nj++) {
                const uint32_t off = (uint32_t)((wn * 64 + nj * 16 + bRow) * ROWB
                                                + (ks * 16 + bK) * 2);
                uint32_t rh[4];
                ldsm_x4(uBh + off, rh);
                bh[nj * 2][0] = rh[0]; bh[nj * 2][1] = rh[1];
                bh[nj * 2 + 1][0] = rh[2]; bh[nj * 2 + 1][1] = rh[3];
            }
#pragma unroll
            for (int mi = 0; mi < 2; mi++) {
                uint32_t ah[4], al[4];
                const uint32_t off = (uint32_t)((wm * 32 + mi * 16 + aRow) * ROWB
                                                + (ks * 16 + aK) * 2);
                ldsm_x4(uAh + off, ah);
                ldsm_x4(uAl + off, al);
#pragma unroll
                for (int ni = 0; ni < 8; ni++) {
                    mma_f16(acc[mi][ni], ah, bh[ni]);
                    mma_f16(acc[mi][ni], al, bh[ni]);
                }
            }
        }
        MBAR_ARRIVE(mb_empty0 + st * 8);
    }

    // Epilogue
    {
        const int g = lane >> 2, t = lane & 3;
#pragma unroll
        for (int mi = 0; mi < 2; mi++) {
#pragma unroll
            for (int half = 0; half < 2; half++) {
                const long r = (long)(rowA + wm * 32 + mi * 16 + g + half * 8);
#pragma unroll
                for (int ni = 0; ni < 8; ni++) {
                    const int col = rowB + wn * 64 + ni * 8 + t * 2;
                    float v0 = acc[mi][ni][half * 2 + 0] * alpha;
                    float v1 = acc[mi][ni][half * 2 + 1] * alpha;
                    if (EPI == 0) {
                        *reinterpret_cast<float2*>(&Cf[zb * sC + r * ldC + col]) =
                            make_float2(v0, v1);
                    } else {
                        __half h0, l0, h1, l1;
                        split_h(v0, h0, l0);
                        split_h(v1, h1, l1);
                        __half2 hp, lp;
                        hp.x = h0; hp.y = h1; lp.x = l0; lp.y = l1;
                        *reinterpret_cast<__half2*>(&Chi[zb * sC + r * ldC + col]) = hp;
                        *reinterpret_cast<__half2*>(&Clo[zb * sC + r * ldC + col]) = lp;
                    }
                }
            }
        }
    }
}

// ---------------------------------------------------------------------------
// x: fp32 -> fp16 hi/lo split
// ---------------------------------------------------------------------------
__global__ __launch_bounds__(256)
void cvt_split_kernel(const float* __restrict__ in, __half* __restrict__ hi,
                      __half* __restrict__ lo, long n)
{
    long i = ((long)blockIdx.x * 256 + threadIdx.x) * 4;
    if (i >= n) return;
    float4 v = *reinterpret_cast<const float4*>(in + i);
    __half h[4], l[4];
    split_h(v.x, h[0], l[0]);
    split_h(v.y, h[1], l[1]);
    split_h(v.z, h[2], l[2]);
    split_h(v.w, h[3], l[3]);
    *reinterpret_cast<uint2*>(hi + i) = *reinterpret_cast<uint2*>(h);
    *reinterpret_cast<uint2*>(lo + i) = *reinterpret_cast<uint2*>(l);
}

// ---------------------------------------------------------------------------
// W fp32 [R,C] -> transposed fp16 hi [C,R] with output row offset
// ---------------------------------------------------------------------------
__global__ __launch_bounds__(256)
void transpose_cvt_w(const float* __restrict__ in, __half* __restrict__ hi,
                     int R, int C, int roff)
{
    __shared__ float t[32][33];
    const int rb = blockIdx.y * 32, cb = blockIdx.x * 32;
    const int x = threadIdx.x, y = threadIdx.y;
#pragma unroll
    for (int j = 0; j < 32; j += 8)
        t[y + j][x] = in[(long)(rb + y + j) * C + cb + x];
    __syncthreads();
#pragma unroll
    for (int j = 0; j < 32; j += 8)
        hi[(long)(roff + cb + y + j) * R + rb + x] = __float2half_rn(t[x][y + j]);
}

// ---------------------------------------------------------------------------
// fp16 transpose: in [R,C] region (ld ldIn) -> out [C,R] (ld R), batched via z
// ---------------------------------------------------------------------------
__global__ __launch_bounds__(256)
void transpose_h_kernel(const __half* __restrict__ in, __half* __restrict__ out,
                        int R, int ldIn, long sIn, long sOut)
{
    __shared__ __half t[32][34];
    in  += (long)blockIdx.z * sIn;
    out += (long)blockIdx.z * sOut;
    const int rb = blockIdx.y * 32, cb = blockIdx.x * 32;
    const int x = threadIdx.x, y = threadIdx.y;
#pragma unroll
    for (int j = 0; j < 32; j += 8)
        t[y + j][x] = in[(long)(rb + y + j) * ldIn + cb + x];
    __syncthreads();
#pragma unroll
    for (int j = 0; j < 32; j += 8)
        out[(long)(cb + y + j) * R + rb + x] = t[x][y + j];
}

// ---------------------------------------------------------------------------
// Row softmax over SEQ cols, fp32 in -> fp16 hi/lo pair out. 256 thr/row.
// ---------------------------------------------------------------------------
__global__ __launch_bounds__(256)
void softmax_pair_kernel(const float* __restrict__ S, __half* __restrict__ Ph,
                         __half* __restrict__ Pl)
{
    const float* p = S + (long)blockIdx.x * SEQ;
    __half* ph = Ph + (long)blockIdx.x * SEQ;
    __half* pl = Pl + (long)blockIdx.x * SEQ;
    const int tid  = threadIdx.x;
    const int lane = tid & 31;
    const int warp = tid >> 5;
    __shared__ float red[8];

    float4 u0 = *reinterpret_cast<const float4*>(&p[tid * 8]);
    float4 u1 = *reinterpret_cast<const float4*>(&p[tid * 8 + 4]);
    float v[8] = {u0.x, u0.y, u0.z, u0.w, u1.x, u1.y, u1.z, u1.w};

    float m = v[0];
#pragma unroll
    for (int i = 1; i < 8; i++) m = fmaxf(m, v[i]);
#pragma unroll
    for (int o = 16; o > 0; o >>= 1) m = fmaxf(m, __shfl_xor_sync(0xffffffffu, m, o));
    if (lane == 0) red[warp] = m;
    __syncthreads();
    m = red[0];
#pragma unroll
    for (int i = 1; i < 8; i++) m = fmaxf(m, red[i]);
    __syncthreads();

    float s = 0.0f;
#pragma unroll
    for (int i = 0; i < 8; i++) { v[i] = __expf(v[i] - m); s += v[i]; }
#pragma unroll
    for (int o = 16; o > 0; o >>= 1) s += __shfl_xor_sync(0xffffffffu, s, o);
    if (lane == 0) red[warp] = s;
    __syncthreads();
    s = red[0];
#pragma unroll
    for (int i = 1; i < 8; i++) s += red[i];

    const float inv = __frcp_rn(s);
    __half h[8], l[8];
#pragma unroll
    for (int i = 0; i < 8; i++) split_h(v[i] * inv, h[i], l[i]);
    *reinterpret_cast<uint4*>(&ph[tid * 8]) = *reinterpret_cast<uint4*>(h);
    *reinterpret_cast<uint4*>(&pl[tid * 8]) = *reinterpret_cast<uint4*>(l);
}

// ---------------------------------------------------------------------------
extern "C" void kernel_launch(void* const* d_in, const int* in_sizes, int n_in,
                              void* d_out, int out_size)
{
    const float* x  = (const float*)d_in[0];
    const float* Wq = (const float*)d_in[1];
    const float* Wk = (const float*)d_in[2];
    const float* Wv = (const float*)d_in[3];
    float* out = (float*)d_out;

    __half *xh, *xl, *WTh, *QKVh, *QKVl, *Vth, *Ph, *Pl;
    float* S;
    cudaGetSymbolAddress((void**)&xh,   g_xh);
    cudaGetSymbolAddress((void**)&xl,   g_xl);
    cudaGetSymbolAddress((void**)&WTh,  g_WTh);
    cudaGetSymbolAddress((void**)&QKVh, g_QKVh);
    cudaGetSymbolAddress((void**)&QKVl, g_QKVl);
    cudaGetSymbolAddress((void**)&Vth,  g_Vth);
    cudaGetSymbolAddress((void**)&Ph,   g_Ph);
    cudaGetSymbolAddress((void**)&Pl,   g_Pl);
    cudaGetSymbolAddress((void**)&S,    g_S);

    cudaFuncSetAttribute(tc_gemm13<0>, cudaFuncAttributeMaxDynamicSharedMemorySize, SMEMB);
    cudaFuncSetAttribute(tc_gemm13<1>, cudaFuncAttributeMaxDynamicSharedMemorySize, SMEMB);

    const dim3 gemmBlk(512);
    const dim3 blk256(256);
    const dim3 tblk(32, 8);
    const int M_proj = BATCH * SEQ;      // 16384
    const long nx = (long)M_proj * DIM;

    // 1) Split x -> fp16 hi/lo
    cvt_split_kernel<<<(unsigned)((nx / 4 + 255) / 256), blk256>>>(x, xh, xl, nx);

    // 2) Transpose weights -> WTh [1536, 512] fp16 (B-side needs hi only)
    {
        dim3 g(DIM / 32, DIM / 32);
        transpose_cvt_w<<<g, tblk>>>(Wq, WTh, DIM, DIM, 0);
        transpose_cvt_w<<<g, tblk>>>(Wk, WTh, DIM, DIM, DIM);
        transpose_cvt_w<<<g, tblk>>>(Wv, WTh, DIM, DIM, 2 * DIM);
    }

    // 3) Fused QKV projection: QKV[16384,1536] = x @ WT^T (fp16 pair out)
    {
        dim3 g(NQKV / 128, M_proj / 128, 1);
        tc_gemm13<1><<<g, gemmBlk, SMEMB>>>(xh, xl, WTh,
                                            nullptr, QKVh, QKVl,
                                            M_proj, NQKV, DIM, DIM, DIM, NQKV,
                                            0, 0, 0, 1.0f);
    }

    // 4) Transpose V-hi (QKVh cols 1024..1535) -> Vth [512, 2048], per batch
    {
        dim3 g(DIM / 32, SEQ / 32, BATCH);
        transpose_h_kernel<<<g, tblk>>>(QKVh + 2 * DIM, Vth, SEQ, NQKV,
                                        (long)SEQ * NQKV, (long)DIM * SEQ);
    }

    // 5) Scores: S[b] = Q[b] @ K[b]^T / sqrt(D)  (Q split pair, K hi; fp32 out)
    {
        const float scale = 0.044194173824159216f;  // 1/sqrt(512)
        dim3 g(SEQ / 128, SEQ / 128, BATCH);
        tc_gemm13<0><<<g, gemmBlk, SMEMB>>>(QKVh, QKVl, QKVh + DIM,
                                            S, nullptr, nullptr,
                                            SEQ, SEQ, DIM, NQKV, NQKV, SEQ,
                                            (long)SEQ * NQKV, (long)SEQ * NQKV,
                                            (long)SEQ * SEQ, scale);
    }

    // 6) Softmax -> P fp16 pair
    softmax_pair_kernel<<<BATCH * SEQ, blk256>>>(S, Ph, Pl);

    // 7) out[b] = P[b] @ Vt[b]^T  (P split pair, V hi; fp32 out)
    {
        dim3 g(DIM / 128, SEQ / 128, BATCH);
        tc_gemm13<0><<<g, gemmBlk, SMEMB>>>(Ph, Pl, Vth,
                                            out, nullptr, nullptr,
                                            SEQ, DIM, SEQ, SEQ, SEQ, DIM,
                                            (long)SEQ * SEQ, (long)DIM * SEQ,
                                            (long)SEQ * DIM, 1.0f);
    }
}

// round 17
// speedup vs baseline: 2.0650x; 1.1196x over previous
#include <cuda_runtime.h>
#include <cuda_fp16.h>
#include <cstdint>

#define BATCH 8
#define SEQ   2048
#define DIM   512
#define NQKV  1536   // 3*DIM

// ---------------------------------------------------------------------------
// Scratch (device globals) — fp16 pre-split operands
// ---------------------------------------------------------------------------
__device__ __align__(16) __half g_xh  [(long)BATCH * SEQ * DIM];   // 16 MB
__device__ __align__(16) __half g_xl  [(long)BATCH * SEQ * DIM];   // 16 MB
__device__ __align__(16) __half g_WTh [(long)NQKV * DIM];          // 1.5 MB
__device__ __align__(16) __half g_QKVh[(long)BATCH * SEQ * NQKV];  // 48 MB
__device__ __align__(16) __half g_QKVl[(long)BATCH * SEQ * NQKV];  // 48 MB
__device__ __align__(16) __half g_Vth [(long)BATCH * DIM * SEQ];   // 16 MB
__device__ __align__(16) __half g_Ph  [(long)BATCH * SEQ * SEQ];   // 64 MB
__device__ __align__(16) float  g_S   [(long)BATCH * SEQ * SEQ];   // 128 MB

// ---------------------------------------------------------------------------
// PTX helpers (baseline ISA: ldmatrix, mma.sync, cp.async, mbarrier)
// ---------------------------------------------------------------------------
__device__ __forceinline__ uint32_t smem_u32(const void* p) {
    uint32_t a;
    asm("{ .reg .u64 t; cvta.to.shared.u64 t, %1; cvt.u32.u64 %0, t; }"
        : "=r"(a) : "l"(p));
    return a;
}
__device__ __forceinline__ void ldsm_x4(uint32_t addr, uint32_t* r) {
    asm volatile("ldmatrix.sync.aligned.m8n8.x4.shared.b16 {%0,%1,%2,%3}, [%4];"
                 : "=r"(r[0]), "=r"(r[1]), "=r"(r[2]), "=r"(r[3]) : "r"(addr));
}
__device__ __forceinline__ void mma_f16(float* c, const uint32_t* a, const uint32_t* b) {
    asm volatile(
        "mma.sync.aligned.m16n8k16.row.col.f32.f16.f16.f32 "
        "{%0,%1,%2,%3}, {%4,%5,%6,%7}, {%8,%9}, {%0,%1,%2,%3};"
        : "+f"(c[0]), "+f"(c[1]), "+f"(c[2]), "+f"(c[3])
        : "r"(a[0]), "r"(a[1]), "r"(a[2]), "r"(a[3]), "r"(b[0]), "r"(b[1]));
}
__device__ __forceinline__ void cp16(uint32_t dst, const void* src) {
    asm volatile("cp.async.cg.shared.global [%0], [%1], 16;" :: "r"(dst), "l"(src));
}
#define CP_COMMIT() asm volatile("cp.async.commit_group;" ::: "memory")
#define CP_WAIT0()  asm volatile("cp.async.wait_group 0;" ::: "memory")

#define MBAR_INIT(mbar, cnt) \
    asm volatile("mbarrier.init.shared.b64 [%0], %1;" :: "r"(mbar), "r"((uint32_t)(cnt)) : "memory")
#define MBAR_ARRIVE(mbar) \
    asm volatile("mbarrier.arrive.shared.b64 _, [%0];" :: "r"(mbar) : "memory")
#define MBAR_WAIT(mbar_addr, parity) do {                                          \
    uint32_t _m = (mbar_addr); uint32_t _p = (parity); uint32_t _done;             \
    asm volatile("{ .reg .pred p; mbarrier.try_wait.parity.acquire.cta.shared::cta.b64 p, [%1], %2; " \
                 "selp.b32 %0, 1, 0, p; }" : "=r"(_done) : "r"(_m), "r"(_p) : "memory"); \
    if (!_done) {                                                                  \
        asm volatile("{ .reg .pred P1; WL_%=: mbarrier.try_wait.parity.acquire.cta.shared::cta.b64 P1, [%0], %1, 0x989680; " \
                     "@P1 bra.uni WD_%=; bra.uni WL_%=; WD_%=: }"                  \
                     :: "r"(_m), "r"(_p) : "memory");                              \
    }                                                                              \
} while (0)

__device__ __forceinline__ void split_h(float v, __half& h, __half& l) {
    h = __float2half_rn(v);
    l = __float2half_rn(v - __half2float(h));
}

// ---------------------------------------------------------------------------
// Tensor-core GEMM, WARP-SPECIALIZED, mbarrier handoff, FP16 SPLIT-A with
// TERMS = 2 (A = Ah+Al) or 1 (A = Ah only). B = Bh (fp16), fp32 accumulate.
// CTA tile 128x128, K-chunk 64, double-buffered. 512 threads: warps 0-7
// consumers (4M x 2N grid of 32x64 tiles), warps 8-15 producers (pure
// cp.async). EPI 0: fp32 out; EPI 1: fp16 hi/lo pair out.
// ---------------------------------------------------------------------------
#define KC     64
#define ROWB   144                 // 64 fp16 = 128B + 16B pad: conflict-free ldsm
#define TILEB  (128 * ROWB)        // 18432
#define STAGEB (3 * TILEB)         // Ah, Al, Bh = 55296
#define MBAR_OFF (2 * STAGEB)      // 110592
#define SMEMB  (MBAR_OFF + 64)

template <int EPI, int TERMS>
__global__ __launch_bounds__(512, 1)
void tc_gemm14(const __half* __restrict__ Ah, const __half* __restrict__ Al,
               const __half* __restrict__ Bh,
               float* __restrict__ Cf,
               __half* __restrict__ Chi, __half* __restrict__ Clo,
               int M, int N, int K, int ldA, int ldB, int ldC,
               long sA, long sB, long sC, float alpha)
{
    extern __shared__ __align__(16) char smem[];
    const uint32_t sbase = smem_u32(smem);

    const long zb = blockIdx.z;
    Ah += zb * sA;
    if (TERMS == 2) Al += zb * sA;
    Bh += zb * sB;

    const int tid  = threadIdx.x;
    const int wid  = tid >> 5;
    const int lane = tid & 31;
    const bool consumer = (wid < 8);

    const int rowA = blockIdx.y * 128;
    const int rowB = blockIdx.x * 128;
    const int nchunk = K / KC;

    const uint32_t mb_full0  = sbase + MBAR_OFF;
    const uint32_t mb_empty0 = sbase + MBAR_OFF + 16;

    if (tid == 0) {
        MBAR_INIT(mb_full0,       256);
        MBAR_INIT(mb_full0 + 8,   256);
        MBAR_INIT(mb_empty0,      256);
        MBAR_INIT(mb_empty0 + 8,  256);
    }
    __syncthreads();

    const int ptid = tid - 256;

    if (!consumer) {
        // ================= PRODUCER LOOP =================
        for (int c = 0; c < nchunk; c++) {
            const int st = c & 1;
            const uint32_t par = ((c >> 1) & 1) ^ 1;  // first two waits pass
            MBAR_WAIT(mb_empty0 + st * 8, par);
            const int kb = c * KC;
            const uint32_t base = sbase + st * STAGEB;
#pragma unroll
            for (int i = 0; i < 4; i++) {
                const int cid = ptid + i * 256;        // 0..1023
                const int r   = cid >> 3;              // row 0..127
                const int sg  = cid & 7;               // 16B segment
                const uint32_t off = (uint32_t)(r * ROWB + sg * 16);
                cp16(base + 0 * TILEB + off, Ah + (long)(rowA + r) * ldA + kb + sg * 8);
                if (TERMS == 2)
                    cp16(base + 1 * TILEB + off, Al + (long)(rowA + r) * ldA + kb + sg * 8);
                cp16(base + 2 * TILEB + off, Bh + (long)(rowB + r) * ldB + kb + sg * 8);
            }
            CP_COMMIT();
            CP_WAIT0();
            MBAR_ARRIVE(mb_full0 + st * 8);
        }
        return;
    }

    // ---- consumer: 4M x 2N grid of 32x64 warp tiles ----
    const int wm = wid & 3;    // 4 warps along M (32 rows each)
    const int wn = wid >> 2;   // 2 warps along N (64 cols each)
    const int aRow = lane & 15;
    const int aK   = (lane >> 4) * 8;
    const int bRow = (lane & 7) + ((lane >> 4) & 1) * 8;
    const int bK   = ((lane >> 3) & 1) * 8;

    float acc[2][8][4];
#pragma unroll
    for (int i = 0; i < 2; i++)
#pragma unroll
        for (int j = 0; j < 8; j++)
#pragma unroll
            for (int k = 0; k < 4; k++) acc[i][j][k] = 0.0f;

    for (int c = 0; c < nchunk; c++) {
        const int st = c & 1;
        MBAR_WAIT(mb_full0 + st * 8, (c >> 1) & 1);

        const uint32_t uAh = sbase + st * STAGEB;
        const uint32_t uAl = uAh + TILEB;
        const uint32_t uBh = uAh + 2 * TILEB;
#pragma unroll
        for (int ks = 0; ks < 4; ks++) {
            uint32_t bh[8][2];
#pragma unroll
            for (int nj = 0; nj < 4; nj++) {
                const uint32_t off = (uint32_t)((wn * 64 + nj * 16 + bRow) * ROWB
                                                + (ks * 16 + bK) * 2);
                uint32_t rh[4];
                ldsm_x4(uBh + off, rh);
                bh[nj * 2][0] = rh[0]; bh[nj * 2][1] = rh[1];
                bh[nj * 2 + 1][0] = rh[2]; bh[nj * 2 + 1][1] = rh[3];
            }
#pragma unroll
            for (int mi = 0; mi < 2; mi++) {
                uint32_t ah[4], al[4];
                const uint32_t off = (uint32_t)((wm * 32 + mi * 16 + aRow) * ROWB
                                                + (ks * 16 + aK) * 2);
                ldsm_x4(uAh + off, ah);
                if (TERMS == 2) ldsm_x4(uAl + off, al);
#pragma unroll
                for (int ni = 0; ni < 8; ni++) {
                    mma_f16(acc[mi][ni], ah, bh[ni]);
                    if (TERMS == 2) mma_f16(acc[mi][ni], al, bh[ni]);
                }
            }
        }
        MBAR_ARRIVE(mb_empty0 + st * 8);
    }

    // Epilogue
    {
        const int g = lane >> 2, t = lane & 3;
#pragma unroll
        for (int mi = 0; mi < 2; mi++) {
#pragma unroll
            for (int half = 0; half < 2; half++) {
                const long r = (long)(rowA + wm * 32 + mi * 16 + g + half * 8);
#pragma unroll
                for (int ni = 0; ni < 8; ni++) {
                    const int col = rowB + wn * 64 + ni * 8 + t * 2;
                    float v0 = acc[mi][ni][half * 2 + 0] * alpha;
                    float v1 = acc[mi][ni][half * 2 + 1] * alpha;
                    if (EPI == 0) {
                        *reinterpret_cast<float2*>(&Cf[zb * sC + r * ldC + col]) =
                            make_float2(v0, v1);
                    } else {
                        __half h0, l0, h1, l1;
                        split_h(v0, h0, l0);
                        split_h(v1, h1, l1);
                        __half2 hp, lp;
                        hp.x = h0; hp.y = h1; lp.x = l0; lp.y = l1;
                        *reinterpret_cast<__half2*>(&Chi[zb * sC + r * ldC + col]) = hp;
                        *reinterpret_cast<__half2*>(&Clo[zb * sC + r * ldC + col]) = lp;
                    }
                }
            }
        }
    }
}

// ---------------------------------------------------------------------------
// x: fp32 -> fp16 hi/lo split
// ---------------------------------------------------------------------------
__global__ __launch_bounds__(256)
void cvt_split_kernel(const float* __restrict__ in, __half* __restrict__ hi,
                      __half* __restrict__ lo, long n)
{
    long i = ((long)blockIdx.x * 256 + threadIdx.x) * 4;
    if (i >= n) return;
    float4 v = *reinterpret_cast<const float4*>(in + i);
    __half h[4], l[4];
    split_h(v.x, h[0], l[0]);
    split_h(v.y, h[1], l[1]);
    split_h(v.z, h[2], l[2]);
    split_h(v.w, h[3], l[3]);
    *reinterpret_cast<uint2*>(hi + i) = *reinterpret_cast<uint2*>(h);
    *reinterpret_cast<uint2*>(lo + i) = *reinterpret_cast<uint2*>(l);
}

// ---------------------------------------------------------------------------
// W fp32 [R,C] -> transposed fp16 hi [C,R] with output row offset
// ---------------------------------------------------------------------------
__global__ __launch_bounds__(256)
void transpose_cvt_w(const float* __restrict__ in, __half* __restrict__ hi,
                     int R, int C, int roff)
{
    __shared__ float t[32][33];
    const int rb = blockIdx.y * 32, cb = blockIdx.x * 32;
    const int x = threadIdx.x, y = threadIdx.y;
#pragma unroll
    for (int j = 0; j < 32; j += 8)
        t[y + j][x] = in[(long)(rb + y + j) * C + cb + x];
    __syncthreads();
#pragma unroll
    for (int j = 0; j < 32; j += 8)
        hi[(long)(roff + cb + y + j) * R + rb + x] = __float2half_rn(t[x][y + j]);
}

// ---------------------------------------------------------------------------
// fp16 transpose: in [R,C] region (ld ldIn) -> out [C,R] (ld R), batched via z
// ---------------------------------------------------------------------------
__global__ __launch_bounds__(256)
void transpose_h_kernel(const __half* __restrict__ in, __half* __restrict__ out,
                        int R, int ldIn, long sIn, long sOut)
{
    __shared__ __half t[32][34];
    in  += (long)blockIdx.z * sIn;
    out += (long)blockIdx.z * sOut;
    const int rb = blockIdx.y * 32, cb = blockIdx.x * 32;
    const int x = threadIdx.x, y = threadIdx.y;
#pragma unroll
    for (int j = 0; j < 32; j += 8)
        t[y + j][x] = in[(long)(rb + y + j) * ldIn + cb + x];
    __syncthreads();
#pragma unroll
    for (int j = 0; j < 32; j += 8)
        out[(long)(cb + y + j) * R + rb + x] = t[x][y + j];
}

// ---------------------------------------------------------------------------
// Row softmax over SEQ cols, fp32 in -> fp16 hi out. 256 thr/row.
// ---------------------------------------------------------------------------
__global__ __launch_bounds__(256)
void softmax_h_kernel(const float* __restrict__ S, __half* __restrict__ Ph)
{
    const float* p = S + (long)blockIdx.x * SEQ;
    __half* ph = Ph + (long)blockIdx.x * SEQ;
    const int tid  = threadIdx.x;
    const int lane = tid & 31;
    const int warp = tid >> 5;
    __shared__ float red[8];

    float4 u0 = *reinterpret_cast<const float4*>(&p[tid * 8]);
    float4 u1 = *reinterpret_cast<const float4*>(&p[tid * 8 + 4]);
    float v[8] = {u0.x, u0.y, u0.z, u0.w, u1.x, u1.y, u1.z, u1.w};

    float m = v[0];
#pragma unroll
    for (int i = 1; i < 8; i++) m = fmaxf(m, v[i]);
#pragma unroll
    for (int o = 16; o > 0; o >>= 1) m = fmaxf(m, __shfl_xor_sync(0xffffffffu, m, o));
    if (lane == 0) red[warp] = m;
    __syncthreads();
    m = red[0];
#pragma unroll
    for (int i = 1; i < 8; i++) m = fmaxf(m, red[i]);
    __syncthreads();

    float s = 0.0f;
#pragma unroll
    for (int i = 0; i < 8; i++) { v[i] = __expf(v[i] - m); s += v[i]; }
#pragma unroll
    for (int o = 16; o > 0; o >>= 1) s += __shfl_xor_sync(0xffffffffu, s, o);
    if (lane == 0) red[warp] = s;
    __syncthreads();
    s = red[0];
#pragma unroll
    for (int i = 1; i < 8; i++) s += red[i];

    const float inv = __frcp_rn(s);
    __half h[8];
#pragma unroll
    for (int i = 0; i < 8; i++) h[i] = __float2half_rn(v[i] * inv);
    *reinterpret_cast<uint4*>(&ph[tid * 8]) = *reinterpret_cast<uint4*>(h);
}

// ---------------------------------------------------------------------------
extern "C" void kernel_launch(void* const* d_in, const int* in_sizes, int n_in,
                              void* d_out, int out_size)
{
    const float* x  = (const float*)d_in[0];
    const float* Wq = (const float*)d_in[1];
    const float* Wk = (const float*)d_in[2];
    const float* Wv = (const float*)d_in[3];
    float* out = (float*)d_out;

    __half *xh, *xl, *WTh, *QKVh, *QKVl, *Vth, *Ph;
    float* S;
    cudaGetSymbolAddress((void**)&xh,   g_xh);
    cudaGetSymbolAddress((void**)&xl,   g_xl);
    cudaGetSymbolAddress((void**)&WTh,  g_WTh);
    cudaGetSymbolAddress((void**)&QKVh, g_QKVh);
    cudaGetSymbolAddress((void**)&QKVl, g_QKVl);
    cudaGetSymbolAddress((void**)&Vth,  g_Vth);
    cudaGetSymbolAddress((void**)&Ph,   g_Ph);
    cudaGetSymbolAddress((void**)&S,    g_S);

    cudaFuncSetAttribute(tc_gemm14<0, 2>, cudaFuncAttributeMaxDynamicSharedMemorySize, SMEMB);
    cudaFuncSetAttribute(tc_gemm14<1, 2>, cudaFuncAttributeMaxDynamicSharedMemorySize, SMEMB);
    cudaFuncSetAttribute(tc_gemm14<0, 1>, cudaFuncAttributeMaxDynamicSharedMemorySize, SMEMB);

    const dim3 gemmBlk(512);
    const dim3 blk256(256);
    const dim3 tblk(32, 8);
    const int M_proj = BATCH * SEQ;      // 16384
    const long nx = (long)M_proj * DIM;

    // 1) Split x -> fp16 hi/lo
    cvt_split_kernel<<<(unsigned)((nx / 4 + 255) / 256), blk256>>>(x, xh, xl, nx);

    // 2) Transpose weights -> WTh [1536, 512] fp16 (B-side: hi only)
    {
        dim3 g(DIM / 32, DIM / 32);
        transpose_cvt_w<<<g, tblk>>>(Wq, WTh, DIM, DIM, 0);
        transpose_cvt_w<<<g, tblk>>>(Wk, WTh, DIM, DIM, DIM);
        transpose_cvt_w<<<g, tblk>>>(Wv, WTh, DIM, DIM, 2 * DIM);
    }

    // 3) Fused QKV projection: QKV[16384,1536] = x @ WT^T (2-term; fp16 pair out)
    {
        dim3 g(NQKV / 128, M_proj / 128, 1);
        tc_gemm14<1, 2><<<g, gemmBlk, SMEMB>>>(xh, xl, WTh,
                                               nullptr, QKVh, QKVl,
                                               M_proj, NQKV, DIM, DIM, DIM, NQKV,
                                               0, 0, 0, 1.0f);
    }

    // 4) Transpose V-hi (QKVh cols 1024..1535) -> Vth [512, 2048], per batch
    {
        dim3 g(DIM / 32, SEQ / 32, BATCH);
        transpose_h_kernel<<<g, tblk>>>(QKVh + 2 * DIM, Vth, SEQ, NQKV,
                                        (long)SEQ * NQKV, (long)DIM * SEQ);
    }

    // 5) Scores: S[b] = Q[b] @ K[b]^T / sqrt(D)  (2-term: Q split, K hi; fp32 out)
    {
        const float scale = 0.044194173824159216f;  // 1/sqrt(512)
        dim3 g(SEQ / 128, SEQ / 128, BATCH);
        tc_gemm14<0, 2><<<g, gemmBlk, SMEMB>>>(QKVh, QKVl, QKVh + DIM,
                                               S, nullptr, nullptr,
                                               SEQ, SEQ, DIM, NQKV, NQKV, SEQ,
                                               (long)SEQ * NQKV, (long)SEQ * NQKV,
                                               (long)SEQ * SEQ, scale);
    }

    // 6) Softmax -> P fp16 hi only
    softmax_h_kernel<<<BATCH * SEQ, blk256>>>(S, Ph);

    // 7) out[b] = P[b] @ Vt[b]^T  (1-TERM: P hi, V hi; fp32 out)
    {
        dim3 g(DIM / 128, SEQ / 128, BATCH);
        tc_gemm14<0, 1><<<g, gemmBlk, SMEMB>>>(Ph, nullptr, Vth,
                                               out, nullptr, nullptr,
                                               SEQ, DIM, SEQ, SEQ, SEQ, DIM,
                                               (long)SEQ * SEQ, (long)DIM * SEQ,
                                               (long)SEQ * DIM, 1.0f);
    }
}